// round 3
// baseline (speedup 1.0000x reference)
#include <cuda_runtime.h>
#include <math.h>

// Problem constants
namespace {
constexpr int B_  = 8;
constexpr int N_  = 2048;
constexpr int M_  = 2048;
constexpr int C_  = 512;
constexpr int H_  = 8;
constexpr int DK_ = 64;
constexpr int RX = B_ * N_;   // 16384 query rows
constexpr int RY = B_ * M_;   // 16384 key rows
constexpr float SCALE = 0.125f;  // 1/sqrt(64)
}

// Scratch (device globals: allocation-free per harness rules)
__device__ float g_xn[(size_t)RX * C_];
__device__ float g_yn[(size_t)RY * C_];
__device__ float g_q [(size_t)RX * C_];
__device__ float g_k [(size_t)RY * C_];
__device__ float g_v [(size_t)RY * C_];
__device__ float g_o [(size_t)RX * C_];
__device__ float g_h [(size_t)RX * C_];
__device__ float g_s [(size_t)B_ * H_ * N_ * M_];  // 1 GB score/weight scratch
__device__ float g_mx[B_ * H_ * N_];
__device__ float g_rl[B_ * H_ * N_];

// ---------------------------------------------------------------------------
// LayerNorm: one block (128 threads) per row of 512 channels, float4 per thread
// ---------------------------------------------------------------------------
__global__ void __launch_bounds__(128) ln_kernel(
    const float* __restrict__ x, const float* __restrict__ gam,
    const float* __restrict__ bet, float* __restrict__ out) {
  const int row = blockIdx.x;
  const int t   = threadIdx.x;
  float4 v = ((const float4*)(x + (size_t)row * C_))[t];
  float s  = v.x + v.y + v.z + v.w;
  float s2 = v.x * v.x + v.y * v.y + v.z * v.z + v.w * v.w;
#pragma unroll
  for (int o = 16; o > 0; o >>= 1) {
    s  += __shfl_xor_sync(0xffffffffu, s, o);
    s2 += __shfl_xor_sync(0xffffffffu, s2, o);
  }
  __shared__ float sa[4], sb[4];
  const int w = t >> 5;
  if ((t & 31) == 0) { sa[w] = s; sb[w] = s2; }
  __syncthreads();
  s  = sa[0] + sa[1] + sa[2] + sa[3];
  s2 = sb[0] + sb[1] + sb[2] + sb[3];
  const float mean = s * (1.f / C_);
  const float var  = s2 * (1.f / C_) - mean * mean;
  const float r    = rsqrtf(var + 1e-5f);
  float4 gg = ((const float4*)gam)[t];
  float4 bb = ((const float4*)bet)[t];
  float4 o;
  o.x = (v.x - mean) * r * gg.x + bb.x;
  o.y = (v.y - mean) * r * gg.y + bb.y;
  o.z = (v.z - mean) * r * gg.z + bb.z;
  o.w = (v.w - mean) * r * gg.w + bb.w;
  ((float4*)(out + (size_t)row * C_))[t] = o;
}

// ---------------------------------------------------------------------------
// Dense GEMM: C[16384,512] = A @ B + bias   (optionally A := A - A2, B^T)
// Block tile 128x64, BK=16, 256 threads, 8x4 micro-tile.
// ---------------------------------------------------------------------------
template <bool TRANSB, bool SUB>
__global__ void __launch_bounds__(256) gemm_kernel(
    const float* __restrict__ A, const float* __restrict__ A2,
    const float* __restrict__ Bm, const float* __restrict__ bias,
    float* __restrict__ Cm) {
  constexpr int BK = 16;
  __shared__ float As[BK][132];   // [k][m] transposed
  __shared__ float Bs[BK][68];    // [k][n]
  const int bm = blockIdx.y * 128;
  const int bn = blockIdx.x * 64;
  const int tid = threadIdx.x;
  const int tx = tid & 15, ty = tid >> 4;
  float acc[8][4] = {};
  for (int k0 = 0; k0 < C_; k0 += BK) {
#pragma unroll
    for (int p = 0; p < 2; p++) {
      const int slot = tid + p * 256;
      const int r = slot >> 2, c4 = slot & 3;
      float4 a = *(const float4*)(A + (size_t)(bm + r) * C_ + k0 + c4 * 4);
      if (SUB) {
        float4 a2 = *(const float4*)(A2 + (size_t)(bm + r) * C_ + k0 + c4 * 4);
        a.x -= a2.x; a.y -= a2.y; a.z -= a2.z; a.w -= a2.w;
      }
      As[c4 * 4 + 0][r] = a.x;
      As[c4 * 4 + 1][r] = a.y;
      As[c4 * 4 + 2][r] = a.z;
      As[c4 * 4 + 3][r] = a.w;
    }
    if (!TRANSB) {
      const int r = tid >> 4, c4 = tid & 15;
      float4 b4 = *(const float4*)(Bm + (size_t)(k0 + r) * C_ + bn + c4 * 4);
      *(float4*)&Bs[r][c4 * 4] = b4;
    } else {
      const int j = tid >> 2, k4 = tid & 3;
      float4 b4 = *(const float4*)(Bm + (size_t)(bn + j) * C_ + k0 + k4 * 4);
      Bs[k4 * 4 + 0][j] = b4.x;
      Bs[k4 * 4 + 1][j] = b4.y;
      Bs[k4 * 4 + 2][j] = b4.z;
      Bs[k4 * 4 + 3][j] = b4.w;
    }
    __syncthreads();
#pragma unroll
    for (int k = 0; k < BK; k++) {
      float4 a0 = *(const float4*)&As[k][ty * 8];
      float4 a1 = *(const float4*)&As[k][ty * 8 + 4];
      float4 b0 = *(const float4*)&Bs[k][tx * 4];
      float av[8] = {a0.x, a0.y, a0.z, a0.w, a1.x, a1.y, a1.z, a1.w};
      float bv[4] = {b0.x, b0.y, b0.z, b0.w};
#pragma unroll
      for (int i = 0; i < 8; i++)
#pragma unroll
        for (int j = 0; j < 4; j++)
          acc[i][j] = fmaf(av[i], bv[j], acc[i][j]);
    }
    __syncthreads();
  }
  float4 bv4 = *(const float4*)(bias + bn + tx * 4);
#pragma unroll
  for (int i = 0; i < 8; i++) {
    float4 o;
    o.x = acc[i][0] + bv4.x;
    o.y = acc[i][1] + bv4.y;
    o.z = acc[i][2] + bv4.z;
    o.w = acc[i][3] + bv4.w;
    *(float4*)(Cm + (size_t)(bm + ty * 8 + i) * C_ + bn + tx * 4) = o;
  }
}

// ---------------------------------------------------------------------------
// Scores: per (b,h) S[n,m] = scale * Q_h[n,:] . K_h[m,:]  (K-dim = 64, fits SMEM)
// Block: 64x64 output tile, 256 threads, 4x4 micro-tile.
// ---------------------------------------------------------------------------
__global__ void __launch_bounds__(256) scores_kernel() {
  __shared__ float Qs[64][68];   // [d][n]
  __shared__ float Ks[64][68];   // [d][m]
  const int bh = blockIdx.z;
  const int b = bh >> 3, h = bh & 7;
  const int n0 = blockIdx.y << 6, m0 = blockIdx.x << 6;
  const int tid = threadIdx.x, tx = tid & 15, ty = tid >> 4;
  const float* qb = g_q + (size_t)(b * N_ + n0) * C_ + h * DK_;
  const float* kb = g_k + (size_t)(b * M_ + m0) * C_ + h * DK_;
#pragma unroll
  for (int p = 0; p < 4; p++) {
    const int slot = tid + p * 256;
    const int r = slot >> 4, c4 = slot & 15;
    float4 q4 = *(const float4*)(qb + (size_t)r * C_ + c4 * 4);
    Qs[c4 * 4 + 0][r] = q4.x;
    Qs[c4 * 4 + 1][r] = q4.y;
    Qs[c4 * 4 + 2][r] = q4.z;
    Qs[c4 * 4 + 3][r] = q4.w;
    float4 k4 = *(const float4*)(kb + (size_t)r * C_ + c4 * 4);
    Ks[c4 * 4 + 0][r] = k4.x;
    Ks[c4 * 4 + 1][r] = k4.y;
    Ks[c4 * 4 + 2][r] = k4.z;
    Ks[c4 * 4 + 3][r] = k4.w;
  }
  __syncthreads();
  float acc[4][4] = {};
#pragma unroll 16
  for (int d = 0; d < DK_; d++) {
    float4 a  = *(const float4*)&Qs[d][ty * 4];
    float4 k4 = *(const float4*)&Ks[d][tx * 4];
    float av[4] = {a.x, a.y, a.z, a.w};
    float kv[4] = {k4.x, k4.y, k4.z, k4.w};
#pragma unroll
    for (int i = 0; i < 4; i++)
#pragma unroll
      for (int j = 0; j < 4; j++)
        acc[i][j] = fmaf(av[i], kv[j], acc[i][j]);
  }
  float* sb = g_s + ((size_t)bh * N_ + n0) * M_ + m0;
#pragma unroll
  for (int i = 0; i < 4; i++) {
    float4 o = {acc[i][0] * SCALE, acc[i][1] * SCALE,
                acc[i][2] * SCALE, acc[i][3] * SCALE};
    *(float4*)(sb + (size_t)(ty * 4 + i) * M_ + tx * 4) = o;
  }
}

// ---------------------------------------------------------------------------
// Per-row softmax stats over m: max and 1/sum(exp).  One 256-thread block/row.
// ---------------------------------------------------------------------------
__global__ void __launch_bounds__(256) stats_kernel() {
  const size_t row = blockIdx.x;
  const float4* sr = (const float4*)(g_s + row * (size_t)M_);
  const int t = threadIdx.x;
  float4 v0 = sr[t], v1 = sr[t + 256];
  float mx = fmaxf(fmaxf(fmaxf(v0.x, v0.y), fmaxf(v0.z, v0.w)),
                   fmaxf(fmaxf(v1.x, v1.y), fmaxf(v1.z, v1.w)));
#pragma unroll
  for (int o = 16; o > 0; o >>= 1)
    mx = fmaxf(mx, __shfl_xor_sync(0xffffffffu, mx, o));
  __shared__ float red[8];
  const int w = t >> 5;
  if ((t & 31) == 0) red[w] = mx;
  __syncthreads();
  float bm = red[0];
#pragma unroll
  for (int i = 1; i < 8; i++) bm = fmaxf(bm, red[i]);
  __syncthreads();
  float s = __expf(v0.x - bm) + __expf(v0.y - bm) + __expf(v0.z - bm) +
            __expf(v0.w - bm) + __expf(v1.x - bm) + __expf(v1.y - bm) +
            __expf(v1.z - bm) + __expf(v1.w - bm);
#pragma unroll
  for (int o = 16; o > 0; o >>= 1) s += __shfl_xor_sync(0xffffffffu, s, o);
  if ((t & 31) == 0) red[w] = s;
  __syncthreads();
  if (t == 0) {
    float tot = red[0] + red[1] + red[2] + red[3] +
                red[4] + red[5] + red[6] + red[7];
    g_mx[row] = bm;
    g_rl[row] = 1.f / tot;
  }
}

// ---------------------------------------------------------------------------
// Cross-head renorm (in place): w_h = p_h / (1e-9 + sum_h p_h), per (b,n,m).
// Each thread handles 4 consecutive m for all 8 heads.
// ---------------------------------------------------------------------------
__global__ void __launch_bounds__(256) renorm_kernel() {
  const size_t idx = (size_t)blockIdx.x * 256 + threadIdx.x;  // over B*N*(M/4)
  const int m4 = (int)(idx & (M_ / 4 - 1));
  const size_t bn = idx >> 9;
  const int n = (int)(bn & (N_ - 1));
  const int b = (int)(bn >> 11);
  float4 p[8];
  size_t off[8];
  float dx = 1e-9f, dy = 1e-9f, dz = 1e-9f, dw = 1e-9f;
#pragma unroll
  for (int h = 0; h < 8; h++) {
    const size_t row = (size_t)(b * H_ + h) * N_ + n;
    const size_t o = row * M_ + (size_t)m4 * 4;
    off[h] = o;
    float4 s = *(const float4*)(g_s + o);
    const float mx = g_mx[row], rl = g_rl[row];
    float4 pv;
    pv.x = __expf(s.x - mx) * rl;
    pv.y = __expf(s.y - mx) * rl;
    pv.z = __expf(s.z - mx) * rl;
    pv.w = __expf(s.w - mx) * rl;
    p[h] = pv;
    dx += pv.x; dy += pv.y; dz += pv.z; dw += pv.w;
  }
  const float ix = 1.f / dx, iy = 1.f / dy, iz = 1.f / dz, iw = 1.f / dw;
#pragma unroll
  for (int h = 0; h < 8; h++) {
    float4 o4 = {p[h].x * ix, p[h].y * iy, p[h].z * iz, p[h].w * iw};
    *(float4*)(g_s + off[h]) = o4;
  }
}

// ---------------------------------------------------------------------------
// AV: per (b,h) O[n, d] = sum_m W[n,m] * V[m, d].  64(n) x 64(d) tile, K over M.
// ---------------------------------------------------------------------------
__global__ void __launch_bounds__(256) av_kernel() {
  __shared__ float Ws[64][68];   // [k(m)][n]
  __shared__ float Vs[64][68];   // [k(m)][d]
  const int bh = blockIdx.y;
  const int b = bh >> 3, h = bh & 7;
  const int n0 = blockIdx.x << 6;
  const int tid = threadIdx.x, tx = tid & 15, ty = tid >> 4;
  const float* wbase = g_s + ((size_t)bh * N_ + n0) * M_;
  const float* vbase = g_v + (size_t)(b * M_) * C_ + h * DK_;
  float acc[4][4] = {};
  for (int m0 = 0; m0 < M_; m0 += 64) {
#pragma unroll
    for (int p = 0; p < 4; p++) {
      const int slot = tid + p * 256;
      const int r = slot >> 4, c4 = slot & 15;
      float4 wv = *(const float4*)(wbase + (size_t)r * M_ + m0 + c4 * 4);
      Ws[c4 * 4 + 0][r] = wv.x;
      Ws[c4 * 4 + 1][r] = wv.y;
      Ws[c4 * 4 + 2][r] = wv.z;
      Ws[c4 * 4 + 3][r] = wv.w;
      float4 vv = *(const float4*)(vbase + (size_t)(m0 + r) * C_ + c4 * 4);
      *(float4*)&Vs[r][c4 * 4] = vv;
    }
    __syncthreads();
#pragma unroll 16
    for (int k = 0; k < 64; k++) {
      float4 a  = *(const float4*)&Ws[k][ty * 4];
      float4 vv = *(const float4*)&Vs[k][tx * 4];
      float av[4] = {a.x, a.y, a.z, a.w};
      float bv[4] = {vv.x, vv.y, vv.z, vv.w};
#pragma unroll
      for (int i = 0; i < 4; i++)
#pragma unroll
        for (int j = 0; j < 4; j++)
          acc[i][j] = fmaf(av[i], bv[j], acc[i][j]);
    }
    __syncthreads();
  }
#pragma unroll
  for (int i = 0; i < 4; i++) {
    float4 o = {acc[i][0], acc[i][1], acc[i][2], acc[i][3]};
    *(float4*)(g_o + (size_t)(b * N_ + n0 + ty * 4 + i) * C_ + h * DK_ + tx * 4) = o;
  }
}

// ---------------------------------------------------------------------------
// Final: out = q + leaky_relu(LN(h))
// ---------------------------------------------------------------------------
__global__ void __launch_bounds__(128) final_kernel(
    const float* __restrict__ gam, const float* __restrict__ bet,
    float* __restrict__ out) {
  const int row = blockIdx.x;
  const int t = threadIdx.x;
  float4 v = ((const float4*)(g_h + (size_t)row * C_))[t];
  float s  = v.x + v.y + v.z + v.w;
  float s2 = v.x * v.x + v.y * v.y + v.z * v.z + v.w * v.w;
#pragma unroll
  for (int o = 16; o > 0; o >>= 1) {
    s  += __shfl_xor_sync(0xffffffffu, s, o);
    s2 += __shfl_xor_sync(0xffffffffu, s2, o);
  }
  __shared__ float sa[4], sb[4];
  const int w = t >> 5;
  if ((t & 31) == 0) { sa[w] = s; sb[w] = s2; }
  __syncthreads();
  s  = sa[0] + sa[1] + sa[2] + sa[3];
  s2 = sb[0] + sb[1] + sb[2] + sb[3];
  const float mean = s * (1.f / C_);
  const float var  = s2 * (1.f / C_) - mean * mean;
  const float r    = rsqrtf(var + 1e-5f);
  float4 gg = ((const float4*)gam)[t];
  float4 bb = ((const float4*)bet)[t];
  float4 q4 = ((const float4*)(g_q + (size_t)row * C_))[t];
  float4 o;
  float y;
  y = (v.x - mean) * r * gg.x + bb.x; y = y > 0.f ? y : 0.02f * y; o.x = q4.x + y;
  y = (v.y - mean) * r * gg.y + bb.y; y = y > 0.f ? y : 0.02f * y; o.y = q4.y + y;
  y = (v.z - mean) * r * gg.z + bb.z; y = y > 0.f ? y : 0.02f * y; o.z = q4.z + y;
  y = (v.w - mean) * r * gg.w + bb.w; y = y > 0.f ? y : 0.02f * y; o.w = q4.w + y;
  ((float4*)(out + (size_t)row * C_))[t] = o;
}

// ---------------------------------------------------------------------------
extern "C" void kernel_launch(void* const* d_in, const int* in_sizes, int n_in,
                              void* d_out, int out_size) {
  (void)in_sizes; (void)n_in; (void)out_size;
  const float* x   = (const float*)d_in[0];
  const float* y   = (const float*)d_in[1];
  const float* lxg = (const float*)d_in[2];
  const float* lxb = (const float*)d_in[3];
  const float* lyg = (const float*)d_in[4];
  const float* lyb = (const float*)d_in[5];
  const float* Wq  = (const float*)d_in[6];
  const float* bq  = (const float*)d_in[7];
  const float* Wk  = (const float*)d_in[8];
  const float* bk  = (const float*)d_in[9];
  const float* Wv  = (const float*)d_in[10];
  const float* bv  = (const float*)d_in[11];
  const float* Wc  = (const float*)d_in[12];
  const float* bc  = (const float*)d_in[13];
  const float* log_ = (const float*)d_in[14];
  const float* lob  = (const float*)d_in[15];
  float* out = (float*)d_out;

  static float *pxn = nullptr, *pyn, *pq, *pk, *pv, *po, *ph;
  if (!pxn) {
    cudaGetSymbolAddress((void**)&pyn, g_yn);
    cudaGetSymbolAddress((void**)&pq,  g_q);
    cudaGetSymbolAddress((void**)&pk,  g_k);
    cudaGetSymbolAddress((void**)&pv,  g_v);
    cudaGetSymbolAddress((void**)&po,  g_o);
    cudaGetSymbolAddress((void**)&ph,  g_h);
    cudaGetSymbolAddress((void**)&pxn, g_xn);  // last: guards re-entry
  }

  ln_kernel<<<RX, 128>>>(x, lxg, lxb, pxn);
  ln_kernel<<<RY, 128>>>(y, lyg, lyb, pyn);

  dim3 gg(C_ / 64, RX / 128);
  gemm_kernel<false, false><<<gg, 256>>>(pxn, nullptr, Wq, bq, pq);
  gemm_kernel<false, false><<<gg, 256>>>(pyn, nullptr, Wk, bk, pk);
  gemm_kernel<false, false><<<gg, 256>>>(pyn, nullptr, Wv, bv, pv);

  scores_kernel<<<dim3(M_ / 64, N_ / 64, B_ * H_), 256>>>();
  stats_kernel<<<B_ * H_ * N_, 256>>>();
  renorm_kernel<<<(unsigned)((size_t)B_ * N_ * (M_ / 4) / 256), 256>>>();
  av_kernel<<<dim3(N_ / 64, B_ * H_), 256>>>();

  gemm_kernel<true, true><<<gg, 256>>>(pq, po, Wc, bc, ph);
  final_kernel<<<RX, 128>>>(log_, lob, out);
}

// round 5
// speedup vs baseline: 1.5250x; 1.5250x over previous
#include <cuda_runtime.h>
#include <cuda_bf16.h>
#include <cstdint>
#include <math.h>

using bf16 = __nv_bfloat16;

namespace {
constexpr int B_  = 8;
constexpr int N_  = 2048;
constexpr int M_  = 2048;
constexpr int C_  = 512;
constexpr int H_  = 8;
constexpr int DK_ = 64;
constexpr int RX = B_ * N_;
constexpr int RY = B_ * M_;
constexpr int SMEM_MMA = 65536;   // 4 tiles of 128x64 bf16
constexpr int SMEM_AV  = 49152;   // 2x(128x64) + 2x(64x64) bf16
}

// ------------------------- scratch (device globals) -------------------------
__device__ float g_q [(size_t)RX * C_];
__device__ float g_k [(size_t)RY * C_];
__device__ float g_v [(size_t)RY * C_];
__device__ float g_o [(size_t)RX * C_];
__device__ float g_h [(size_t)RX * C_];
__device__ float g_s [(size_t)B_ * H_ * N_ * M_];   // 1 GB scores
__device__ float g_mx[B_ * H_ * N_];
__device__ float g_rl[B_ * H_ * N_];
// bf16 hi/lo split operands
__device__ bf16 g_xnh[(size_t)RX * C_], g_xnl[(size_t)RX * C_];
__device__ bf16 g_ynh[(size_t)RY * C_], g_ynl[(size_t)RY * C_];
__device__ bf16 g_qh [(size_t)RX * C_], g_ql [(size_t)RX * C_];   // scaled 1/8
__device__ bf16 g_kh [(size_t)RY * C_], g_kl [(size_t)RY * C_];
__device__ bf16 g_vth[(size_t)B_ * H_ * DK_ * M_], g_vtl[(size_t)B_ * H_ * DK_ * M_];
__device__ bf16 g_dh [(size_t)RX * C_], g_dl [(size_t)RX * C_];   // q - o
__device__ bf16 g_wqh[C_ * C_], g_wql[C_ * C_];
__device__ bf16 g_wkh[C_ * C_], g_wkl[C_ * C_];
__device__ bf16 g_wvh[C_ * C_], g_wvl[C_ * C_];
__device__ bf16 g_wch[C_ * C_], g_wcl[C_ * C_];
__device__ bf16 g_wh [(size_t)B_ * H_ * N_ * M_], g_wl[(size_t)B_ * H_ * N_ * M_];

// ------------------------------- helpers ------------------------------------
__device__ __forceinline__ uint32_t smem_u32(const void* p) {
  uint32_t a;
  asm("{ .reg .u64 t; cvta.to.shared.u64 t, %1; cvt.u32.u64 %0, t; }"
      : "=r"(a) : "l"(p));
  return a;
}
__device__ __forceinline__ uint32_t swz(uint32_t off) {
  return off ^ ((off >> 3) & 0x70);
}
__device__ __forceinline__ void ldmat4(uint32_t* r, uint32_t addr) {
  asm volatile("ldmatrix.sync.aligned.m8n8.x4.shared.b16 {%0,%1,%2,%3}, [%4];"
               : "=r"(r[0]), "=r"(r[1]), "=r"(r[2]), "=r"(r[3]) : "r"(addr));
}
__device__ __forceinline__ void mma16816(float* c, const uint32_t* a,
                                         const uint32_t* b) {
  asm volatile(
      "mma.sync.aligned.m16n8k16.row.col.f32.bf16.bf16.f32 "
      "{%0,%1,%2,%3}, {%4,%5,%6,%7}, {%8,%9}, {%0,%1,%2,%3};"
      : "+f"(c[0]), "+f"(c[1]), "+f"(c[2]), "+f"(c[3])
      : "r"(a[0]), "r"(a[1]), "r"(a[2]), "r"(a[3]), "r"(b[0]), "r"(b[1]));
}
// split float pair into packed hi/lo bf16x2 words
__device__ __forceinline__ void split2(float a, float b, uint32_t& hi, uint32_t& lo) {
  bf16 ha = __float2bfloat16(a), hb = __float2bfloat16(b);
  float ra = a - __bfloat162float(ha);
  float rb = b - __bfloat162float(hb);
  bf16 la = __float2bfloat16(ra), lb = __float2bfloat16(rb);
  hi = (uint32_t)__bfloat16_as_ushort(ha) | ((uint32_t)__bfloat16_as_ushort(hb) << 16);
  lo = (uint32_t)__bfloat16_as_ushort(la) | ((uint32_t)__bfloat16_as_ushort(lb) << 16);
}
// load NROWS x 64 bf16 tile (row-major, stride elems) into SW128-swizzled SMEM
template <int NROWS>
__device__ __forceinline__ void load_tile(char* smem, uint32_t sbase,
                                          const bf16* __restrict__ g,
                                          size_t stride, int tid) {
#pragma unroll
  for (int p = 0; p < NROWS * 8 / 256; p++) {
    const int slot = tid + p * 256;
    const int r = slot >> 3, c = slot & 7;
    const uint32_t bo = (uint32_t)(r * 128 + c * 16);
    uint4 v = *(const uint4*)(g + (size_t)r * stride + c * 8);
    *(uint4*)(smem + sbase + swz(bo)) = v;
  }
}

// ------------------------------- LayerNorm ----------------------------------
__global__ void __launch_bounds__(128) ln_split_kernel(
    const float* __restrict__ x, const float* __restrict__ gam,
    const float* __restrict__ bet, bf16* __restrict__ oh, bf16* __restrict__ ol) {
  const int row = blockIdx.x;
  const int t = threadIdx.x;
  float4 v = ((const float4*)(x + (size_t)row * C_))[t];
  float s  = v.x + v.y + v.z + v.w;
  float s2 = v.x * v.x + v.y * v.y + v.z * v.z + v.w * v.w;
#pragma unroll
  for (int o = 16; o > 0; o >>= 1) {
    s  += __shfl_xor_sync(0xffffffffu, s, o);
    s2 += __shfl_xor_sync(0xffffffffu, s2, o);
  }
  __shared__ float sa[4], sb[4];
  const int w = t >> 5;
  if ((t & 31) == 0) { sa[w] = s; sb[w] = s2; }
  __syncthreads();
  s  = sa[0] + sa[1] + sa[2] + sa[3];
  s2 = sb[0] + sb[1] + sb[2] + sb[3];
  const float mean = s * (1.f / C_);
  const float var  = s2 * (1.f / C_) - mean * mean;
  const float r = rsqrtf(var + 1e-5f);
  float4 gg = ((const float4*)gam)[t];
  float4 bb = ((const float4*)bet)[t];
  float ox = (v.x - mean) * r * gg.x + bb.x;
  float oy = (v.y - mean) * r * gg.y + bb.y;
  float oz = (v.z - mean) * r * gg.z + bb.z;
  float ow = (v.w - mean) * r * gg.w + bb.w;
  uint32_t h0, l0, h1, l1;
  split2(ox, oy, h0, l0);
  split2(oz, ow, h1, l1);
  const size_t off = (size_t)row * C_ + t * 4;
  uint2 hh = {h0, h1}, ll = {l0, l1};
  *(uint2*)(oh + off) = hh;
  *(uint2*)(ol + off) = ll;
}

// ------------------- weight transpose + split (Wq/Wk/Wv) --------------------
__global__ void __launch_bounds__(256) wtrans_kernel(
    const float* __restrict__ W, bf16* __restrict__ th, bf16* __restrict__ tl) {
  __shared__ float t[64][65];
  const int c0 = blockIdx.y * 64, j0 = blockIdx.x * 64;
  const int tid = threadIdx.x;
#pragma unroll
  for (int p = 0; p < 4; p++) {
    const int slot = tid + p * 256;
    const int r = slot >> 4, c4 = slot & 15;
    float4 v = *(const float4*)(W + (size_t)(c0 + r) * C_ + j0 + c4 * 4);
    t[r][c4 * 4 + 0] = v.x; t[r][c4 * 4 + 1] = v.y;
    t[r][c4 * 4 + 2] = v.z; t[r][c4 * 4 + 3] = v.w;
  }
  __syncthreads();
#pragma unroll
  for (int p = 0; p < 4; p++) {
    const int slot = tid + p * 256;
    const int jr = slot >> 4, c4 = slot & 15;
    float v0 = t[c4 * 4 + 0][jr], v1 = t[c4 * 4 + 1][jr];
    float v2 = t[c4 * 4 + 2][jr], v3 = t[c4 * 4 + 3][jr];
    uint32_t h0, l0, h1, l1;
    split2(v0, v1, h0, l0);
    split2(v2, v3, h1, l1);
    const size_t off = (size_t)(j0 + jr) * C_ + c0 + c4 * 4;
    uint2 hh = {h0, h1}, ll = {l0, l1};
    *(uint2*)(th + off) = hh;
    *(uint2*)(tl + off) = ll;
  }
}

// ------------------- elementwise split (Wc and q-o diff) --------------------
template <bool SUB>
__global__ void __launch_bounds__(256) split_kernel(
    const float* __restrict__ a, const float* __restrict__ b,
    bf16* __restrict__ oh, bf16* __restrict__ ol) {
  const size_t i4 = (size_t)blockIdx.x * 256 + threadIdx.x;
  float4 v = ((const float4*)a)[i4];
  if (SUB) {
    float4 w = ((const float4*)b)[i4];
    v.x -= w.x; v.y -= w.y; v.z -= w.z; v.w -= w.w;
  }
  uint32_t h0, l0, h1, l1;
  split2(v.x, v.y, h0, l0);
  split2(v.z, v.w, h1, l1);
  uint2 hh = {h0, h1}, ll = {l0, l1};
  *(uint2*)(oh + i4 * 4) = hh;
  *(uint2*)(ol + i4 * 4) = ll;
}

// --------------------- V transpose to [bh][d][m] bf16 -----------------------
__global__ void __launch_bounds__(256) vtrans_kernel() {
  __shared__ float t[64][65];
  const int bh = blockIdx.y;
  const int b = bh >> 3, h = bh & 7;
  const int m0 = blockIdx.x * 64;
  const int tid = threadIdx.x;
#pragma unroll
  for (int p = 0; p < 4; p++) {
    const int slot = tid + p * 256;
    const int r = slot >> 4, c4 = slot & 15;
    float4 v = *(const float4*)(g_v + (size_t)(b * M_ + m0 + r) * C_ + h * DK_ + c4 * 4);
    t[r][c4 * 4 + 0] = v.x; t[r][c4 * 4 + 1] = v.y;
    t[r][c4 * 4 + 2] = v.z; t[r][c4 * 4 + 3] = v.w;
  }
  __syncthreads();
#pragma unroll
  for (int p = 0; p < 4; p++) {
    const int slot = tid + p * 256;
    const int d = slot >> 4, c4 = slot & 15;
    float v0 = t[c4 * 4 + 0][d], v1 = t[c4 * 4 + 1][d];
    float v2 = t[c4 * 4 + 2][d], v3 = t[c4 * 4 + 3][d];
    uint32_t h0, l0, h1, l1;
    split2(v0, v1, h0, l0);
    split2(v2, v3, h1, l1);
    const size_t off = ((size_t)bh * DK_ + d) * M_ + m0 + c4 * 4;
    uint2 hh = {h0, h1}, ll = {l0, l1};
    *(uint2*)(g_vth + off) = hh;
    *(uint2*)(g_vtl + off) = ll;
  }
}

// ---------------- dense HMMA GEMM: out[16384,512] = A·Bt + bias -------------
// 128x128 CTA tile, 8 warps of 64x32, split-precision 3-MMA.
template <bool WRITE_SPLIT>
__global__ void __launch_bounds__(256) mma_gemm_kernel(
    const bf16* __restrict__ Ahi, const bf16* __restrict__ Alo,
    const bf16* __restrict__ Bhi, const bf16* __restrict__ Blo,
    const float* __restrict__ bias, float* __restrict__ out,
    bf16* __restrict__ ohi, bf16* __restrict__ olo, float oscale) {
  extern __shared__ __align__(128) char smem[];
  const uint32_t sbase = smem_u32(smem);
  const int tid = threadIdx.x, wid = tid >> 5, lane = tid & 31;
  const int bm = blockIdx.y * 128, bn = blockIdx.x * 128;
  constexpr uint32_t AH = 0, AL = 16384, BH = 32768, BL = 49152;
  const int mw = (wid & 1) * 64, nw = (wid >> 1) * 32;
  const int arow = (lane & 7) + (lane & 8);
  const uint32_t akb = (uint32_t)(lane & 16);
  const int brow = (lane & 7) + ((lane & 16) >> 1);
  const uint32_t bkb = (uint32_t)((lane & 8) * 2);
  float acc[4][4][4] = {};
  for (int kb = 0; kb < 8; kb++) {
    const int k0 = kb * 64;
    __syncthreads();
    load_tile<128>(smem, AH, Ahi + (size_t)bm * C_ + k0, C_, tid);
    load_tile<128>(smem, AL, Alo + (size_t)bm * C_ + k0, C_, tid);
    load_tile<128>(smem, BH, Bhi + (size_t)bn * C_ + k0, C_, tid);
    load_tile<128>(smem, BL, Blo + (size_t)bn * C_ + k0, C_, tid);
    __syncthreads();
#pragma unroll
    for (int ks = 0; ks < 4; ks++) {
      uint32_t ah[4][4], al[4][4], bh[4][2], bl[4][2];
#pragma unroll
      for (int mt = 0; mt < 4; mt++) {
        const uint32_t off = (uint32_t)((mw + mt * 16 + arow) * 128) + ks * 32 + akb;
        ldmat4(ah[mt], sbase + AH + swz(off));
        ldmat4(al[mt], sbase + AL + swz(off));
      }
#pragma unroll
      for (int np = 0; np < 2; np++) {
        const uint32_t off = (uint32_t)((nw + np * 16 + brow) * 128) + ks * 32 + bkb;
        uint32_t t4[4];
        ldmat4(t4, sbase + BH + swz(off));
        bh[np * 2][0] = t4[0]; bh[np * 2][1] = t4[1];
        bh[np * 2 + 1][0] = t4[2]; bh[np * 2 + 1][1] = t4[3];
        ldmat4(t4, sbase + BL + swz(off));
        bl[np * 2][0] = t4[0]; bl[np * 2][1] = t4[1];
        bl[np * 2 + 1][0] = t4[2]; bl[np * 2 + 1][1] = t4[3];
      }
#pragma unroll
      for (int mt = 0; mt < 4; mt++)
#pragma unroll
        for (int nt = 0; nt < 4; nt++) {
          mma16816(acc[mt][nt], ah[mt], bh[nt]);
          mma16816(acc[mt][nt], ah[mt], bl[nt]);
          mma16816(acc[mt][nt], al[mt], bh[nt]);
        }
    }
  }
  const int rbase = bm + mw + (lane >> 2);
  const int cbase = bn + nw + (lane & 3) * 2;
#pragma unroll
  for (int mt = 0; mt < 4; mt++)
#pragma unroll
    for (int nt = 0; nt < 4; nt++) {
      const int c = cbase + nt * 8;
      const float b0v = bias[c], b1v = bias[c + 1];
#pragma unroll
      for (int hr = 0; hr < 2; hr++) {
        const int r = rbase + mt * 16 + hr * 8;
        const float v0 = acc[mt][nt][hr * 2] + b0v;
        const float v1 = acc[mt][nt][hr * 2 + 1] + b1v;
        float2 o2 = {v0, v1};
        *(float2*)(out + (size_t)r * C_ + c) = o2;
        if (WRITE_SPLIT) {
          uint32_t hw, lw;
          split2(v0 * oscale, v1 * oscale, hw, lw);
          *(uint32_t*)(ohi + (size_t)r * C_ + c) = hw;
          *(uint32_t*)(olo + (size_t)r * C_ + c) = lw;
        }
      }
    }
}

// --------------------- scores: S[n,m] = (q/8)·k per (b,h) -------------------
__global__ void __launch_bounds__(256) scores_mma_kernel() {
  extern __shared__ __align__(128) char smem[];
  const uint32_t sbase = smem_u32(smem);
  const int tid = threadIdx.x, wid = tid >> 5, lane = tid & 31;
  const int bhz = blockIdx.z, b = bhz >> 3, h = bhz & 7;
  const int n0 = blockIdx.y << 7, m0 = blockIdx.x << 7;
  constexpr uint32_t AH = 0, AL = 16384, BH = 32768, BL = 49152;
  const int mw = (wid & 1) * 64, nw = (wid >> 1) * 32;
  const int arow = (lane & 7) + (lane & 8);
  const uint32_t akb = (uint32_t)(lane & 16);
  const int brow = (lane & 7) + ((lane & 16) >> 1);
  const uint32_t bkb = (uint32_t)((lane & 8) * 2);
  const size_t qoff = (size_t)(b * N_ + n0) * C_ + h * DK_;
  const size_t koff = (size_t)(b * M_ + m0) * C_ + h * DK_;
  load_tile<128>(smem, AH, g_qh + qoff, C_, tid);
  load_tile<128>(smem, AL, g_ql + qoff, C_, tid);
  load_tile<128>(smem, BH, g_kh + koff, C_, tid);
  load_tile<128>(smem, BL, g_kl + koff, C_, tid);
  __syncthreads();
  float acc[4][4][4] = {};
#pragma unroll
  for (int ks = 0; ks < 4; ks++) {
    uint32_t ah[4][4], al[4][4], bh[4][2], bl[4][2];
#pragma unroll
    for (int mt = 0; mt < 4; mt++) {
      const uint32_t off = (uint32_t)((mw + mt * 16 + arow) * 128) + ks * 32 + akb;
      ldmat4(ah[mt], sbase + AH + swz(off));
      ldmat4(al[mt], sbase + AL + swz(off));
    }
#pragma unroll
    for (int np = 0; np < 2; np++) {
      const uint32_t off = (uint32_t)((nw + np * 16 + brow) * 128) + ks * 32 + bkb;
      uint32_t t4[4];
      ldmat4(t4, sbase + BH + swz(off));
      bh[np * 2][0] = t4[0]; bh[np * 2][1] = t4[1];
      bh[np * 2 + 1][0] = t4[2]; bh[np * 2 + 1][1] = t4[3];
      ldmat4(t4, sbase + BL + swz(off));
      bl[np * 2][0] = t4[0]; bl[np * 2][1] = t4[1];
      bl[np * 2 + 1][0] = t4[2]; bl[np * 2 + 1][1] = t4[3];
    }
#pragma unroll
    for (int mt = 0; mt < 4; mt++)
#pragma unroll
      for (int nt = 0; nt < 4; nt++) {
        mma16816(acc[mt][nt], ah[mt], bh[nt]);
        mma16816(acc[mt][nt], ah[mt], bl[nt]);
        mma16816(acc[mt][nt], al[mt], bh[nt]);
      }
  }
  const int rbase = n0 + mw + (lane >> 2);
  const int cbase = m0 + nw + (lane & 3) * 2;
  float* sp = g_s + (size_t)bhz * N_ * M_;
#pragma unroll
  for (int mt = 0; mt < 4; mt++)
#pragma unroll
    for (int nt = 0; nt < 4; nt++) {
#pragma unroll
      for (int hr = 0; hr < 2; hr++) {
        const int r = rbase + mt * 16 + hr * 8;
        const int c = cbase + nt * 8;
        float2 o2 = {acc[mt][nt][hr * 2], acc[mt][nt][hr * 2 + 1]};
        *(float2*)(sp + (size_t)r * M_ + c) = o2;
      }
    }
}

// ---------------------------- softmax row stats -----------------------------
__global__ void __launch_bounds__(256) stats_kernel() {
  const size_t row = blockIdx.x;
  const float4* sr = (const float4*)(g_s + row * (size_t)M_);
  const int t = threadIdx.x;
  float4 v0 = sr[t], v1 = sr[t + 256];
  float mx = fmaxf(fmaxf(fmaxf(v0.x, v0.y), fmaxf(v0.z, v0.w)),
                   fmaxf(fmaxf(v1.x, v1.y), fmaxf(v1.z, v1.w)));
#pragma unroll
  for (int o = 16; o > 0; o >>= 1)
    mx = fmaxf(mx, __shfl_xor_sync(0xffffffffu, mx, o));
  __shared__ float red[8];
  const int w = t >> 5;
  if ((t & 31) == 0) red[w] = mx;
  __syncthreads();
  float bm = red[0];
#pragma unroll
  for (int i = 1; i < 8; i++) bm = fmaxf(bm, red[i]);
  __syncthreads();
  float s = __expf(v0.x - bm) + __expf(v0.y - bm) + __expf(v0.z - bm) +
            __expf(v0.w - bm) + __expf(v1.x - bm) + __expf(v1.y - bm) +
            __expf(v1.z - bm) + __expf(v1.w - bm);
#pragma unroll
  for (int o = 16; o > 0; o >>= 1) s += __shfl_xor_sync(0xffffffffu, s, o);
  if ((t & 31) == 0) red[w] = s;
  __syncthreads();
  if (t == 0) {
    float tot = red[0] + red[1] + red[2] + red[3] + red[4] + red[5] + red[6] + red[7];
    g_mx[row] = bm;
    g_rl[row] = 1.f / tot;
  }
}

// ---------------- cross-head renorm -> bf16 hi/lo weights -------------------
__global__ void __launch_bounds__(256) renorm_kernel() {
  const size_t idx = (size_t)blockIdx.x * 256 + threadIdx.x;
  const int m4 = (int)(idx & (M_ / 4 - 1));
  const size_t bn = idx >> 9;
  const int n = (int)(bn & (N_ - 1));
  const int b = (int)(bn >> 11);
  float4 p[8];
  size_t off[8];
  float dx = 1e-9f, dy = 1e-9f, dz = 1e-9f, dw = 1e-9f;
#pragma unroll
  for (int h = 0; h < 8; h++) {
    const size_t row = (size_t)(b * H_ + h) * N_ + n;
    const size_t o = row * M_ + (size_t)m4 * 4;
    off[h] = o;
    float4 s = *(const float4*)(g_s + o);
    const float mx = g_mx[row], rl = g_rl[row];
    float4 pv;
    pv.x = __expf(s.x - mx) * rl;
    pv.y = __expf(s.y - mx) * rl;
    pv.z = __expf(s.z - mx) * rl;
    pv.w = __expf(s.w - mx) * rl;
    p[h] = pv;
    dx += pv.x; dy += pv.y; dz += pv.z; dw += pv.w;
  }
  const float ix = 1.f / dx, iy = 1.f / dy, iz = 1.f / dz, iw = 1.f / dw;
#pragma unroll
  for (int h = 0; h < 8; h++) {
    uint32_t h0, l0, h1, l1;
    split2(p[h].x * ix, p[h].y * iy, h0, l0);
    split2(p[h].z * iz, p[h].w * iw, h1, l1);
    uint2 hh = {h0, h1}, ll = {l0, l1};
    *(uint2*)(g_wh + off[h]) = hh;
    *(uint2*)(g_wl + off[h]) = ll;
  }
}

// ---------------------- AV: O[n,d] = W·Vt per (b,h) -------------------------
// 128(n) x 64(d), K over M=2048. 8 warps of 32x32.
__global__ void __launch_bounds__(256) av_mma_kernel() {
  extern __shared__ __align__(128) char smem[];
  const uint32_t sbase = smem_u32(smem);
  const int tid = threadIdx.x, wid = tid >> 5, lane = tid & 31;
  const int bhz = blockIdx.y, b = bhz >> 3, h = bhz & 7;
  const int n0 = blockIdx.x << 7;
  constexpr uint32_t WH = 0, WL = 16384, VH = 32768, VL = 40960;
  const int mw = (wid & 3) * 32, nw = (wid >> 2) * 32;
  const int arow = (lane & 7) + (lane & 8);
  const uint32_t akb = (uint32_t)(lane & 16);
  const int brow = (lane & 7) + ((lane & 16) >> 1);
  const uint32_t bkb = (uint32_t)((lane & 8) * 2);
  const size_t wbase = ((size_t)bhz * N_ + n0) * M_;
  const size_t vbase = (size_t)bhz * DK_ * M_;
  float acc[2][4][4] = {};
  for (int kb = 0; kb < 32; kb++) {
    const int k0 = kb * 64;
    __syncthreads();
    load_tile<128>(smem, WH, g_wh + wbase + k0, M_, tid);
    load_tile<128>(smem, WL, g_wl + wbase + k0, M_, tid);
    load_tile<64>(smem, VH, g_vth + vbase + k0, M_, tid);
    load_tile<64>(smem, VL, g_vtl + vbase + k0, M_, tid);
    __syncthreads();
#pragma unroll
    for (int ks = 0; ks < 4; ks++) {
      uint32_t ah[2][4], al[2][4], bh[4][2], bl[4][2];
#pragma unroll
      for (int mt = 0; mt < 2; mt++) {
        const uint32_t off = (uint32_t)((mw + mt * 16 + arow) * 128) + ks * 32 + akb;
        ldmat4(ah[mt], sbase + WH + swz(off));
        ldmat4(al[mt], sbase + WL + swz(off));
      }
#pragma unroll
      for (int np = 0; np < 2; np++) {
        const uint32_t off = (uint32_t)((nw + np * 16 + brow) * 128) + ks * 32 + bkb;
        uint32_t t4[4];
        ldmat4(t4, sbase + VH + swz(off));
        bh[np * 2][0] = t4[0]; bh[np * 2][1] = t4[1];
        bh[np * 2 + 1][0] = t4[2]; bh[np * 2 + 1][1] = t4[3];
        ldmat4(t4, sbase + VL + swz(off));
        bl[np * 2][0] = t4[0]; bl[np * 2][1] = t4[1];
        bl[np * 2 + 1][0] = t4[2]; bl[np * 2 + 1][1] = t4[3];
      }
#pragma unroll
      for (int mt = 0; mt < 2; mt++)
#pragma unroll
        for (int nt = 0; nt < 4; nt++) {
          mma16816(acc[mt][nt], ah[mt], bh[nt]);
          mma16816(acc[mt][nt], ah[mt], bl[nt]);
          mma16816(acc[mt][nt], al[mt], bh[nt]);
        }
    }
  }
  const int rbase = n0 + mw + (lane >> 2);
  const int cbase = nw + (lane & 3) * 2;
#pragma unroll
  for (int mt = 0; mt < 2; mt++)
#pragma unroll
    for (int nt = 0; nt < 4; nt++) {
#pragma unroll
      for (int hr = 0; hr < 2; hr++) {
        const int r = rbase + mt * 16 + hr * 8;
        const int c = cbase + nt * 8;
        float2 o2 = {acc[mt][nt][hr * 2], acc[mt][nt][hr * 2 + 1]};
        *(float2*)(g_o + (size_t)(b * N_ + r) * C_ + h * DK_ + c) = o2;
      }
    }
}

// --------------------- final: out = q + leaky_relu(LN(h)) -------------------
__global__ void __launch_bounds__(128) final_kernel(
    const float* __restrict__ gam, const float* __restrict__ bet,
    float* __restrict__ out) {
  const int row = blockIdx.x;
  const int t = threadIdx.x;
  float4 v = ((const float4*)(g_h + (size_t)row * C_))[t];
  float s  = v.x + v.y + v.z + v.w;
  float s2 = v.x * v.x + v.y * v.y + v.z * v.z + v.w * v.w;
#pragma unroll
  for (int o = 16; o > 0; o >>= 1) {
    s  += __shfl_xor_sync(0xffffffffu, s, o);
    s2 += __shfl_xor_sync(0xffffffffu, s2, o);
  }
  __shared__ float sa[4], sb[4];
  const int w = t >> 5;
  if ((t & 31) == 0) { sa[w] = s; sb[w] = s2; }
  __syncthreads();
  s  = sa[0] + sa[1] + sa[2] + sa[3];
  s2 = sb[0] + sb[1] + sb[2] + sb[3];
  const float mean = s * (1.f / C_);
  const float var  = s2 * (1.f / C_) - mean * mean;
  const float r = rsqrtf(var + 1e-5f);
  float4 gg = ((const float4*)gam)[t];
  float4 bb = ((const float4*)bet)[t];
  float4 q4 = ((const float4*)(g_q + (size_t)row * C_))[t];
  float4 o;
  float y;
  y = (v.x - mean) * r * gg.x + bb.x; y = y > 0.f ? y : 0.02f * y; o.x = q4.x + y;
  y = (v.y - mean) * r * gg.y + bb.y; y = y > 0.f ? y : 0.02f * y; o.y = q4.y + y;
  y = (v.z - mean) * r * gg.z + bb.z; y = y > 0.f ? y : 0.02f * y; o.z = q4.z + y;
  y = (v.w - mean) * r * gg.w + bb.w; y = y > 0.f ? y : 0.02f * y; o.w = q4.w + y;
  ((float4*)(out + (size_t)row * C_))[t] = o;
}

// ---------------------------------------------------------------------------
extern "C" void kernel_launch(void* const* d_in, const int* in_sizes, int n_in,
                              void* d_out, int out_size) {
  (void)in_sizes; (void)n_in; (void)out_size;
  const float* x   = (const float*)d_in[0];
  const float* y   = (const float*)d_in[1];
  const float* lxg = (const float*)d_in[2];
  const float* lxb = (const float*)d_in[3];
  const float* lyg = (const float*)d_in[4];
  const float* lyb = (const float*)d_in[5];
  const float* Wq  = (const float*)d_in[6];
  const float* bq  = (const float*)d_in[7];
  const float* Wk  = (const float*)d_in[8];
  const float* bk  = (const float*)d_in[9];
  const float* Wv  = (const float*)d_in[10];
  const float* bv  = (const float*)d_in[11];
  const float* Wc  = (const float*)d_in[12];
  const float* bc  = (const float*)d_in[13];
  const float* log_ = (const float*)d_in[14];
  const float* lob  = (const float*)d_in[15];
  float* out = (float*)d_out;

  static float *pq = nullptr, *pk, *pv, *po, *ph;
  static bf16 *pxnh, *pxnl, *pynh, *pynl, *pqh, *pql, *pkh, *pkl;
  static bf16 *pwqh, *pwql, *pwkh, *pwkl, *pwvh, *pwvl, *pwch, *pwcl, *pdh, *pdl;
  if (!pq) {
    cudaGetSymbolAddress((void**)&pk,   g_k);
    cudaGetSymbolAddress((void**)&pv,   g_v);
    cudaGetSymbolAddress((void**)&po,   g_o);
    cudaGetSymbolAddress((void**)&ph,   g_h);
    cudaGetSymbolAddress((void**)&pxnh, g_xnh);
    cudaGetSymbolAddress((void**)&pxnl, g_xnl);
    cudaGetSymbolAddress((void**)&pynh, g_ynh);
    cudaGetSymbolAddress((void**)&pynl, g_ynl);
    cudaGetSymbolAddress((void**)&pqh,  g_qh);
    cudaGetSymbolAddress((void**)&pql,  g_ql);
    cudaGetSymbolAddress((void**)&pkh,  g_kh);
    cudaGetSymbolAddress((void**)&pkl,  g_kl);
    cudaGetSymbolAddress((void**)&pwqh, g_wqh);
    cudaGetSymbolAddress((void**)&pwql, g_wql);
    cudaGetSymbolAddress((void**)&pwkh, g_wkh);
    cudaGetSymbolAddress((void**)&pwkl, g_wkl);
    cudaGetSymbolAddress((void**)&pwvh, g_wvh);
    cudaGetSymbolAddress((void**)&pwvl, g_wvl);
    cudaGetSymbolAddress((void**)&pwch, g_wch);
    cudaGetSymbolAddress((void**)&pwcl, g_wcl);
    cudaGetSymbolAddress((void**)&pdh,  g_dh);
    cudaGetSymbolAddress((void**)&pdl,  g_dl);
    cudaFuncSetAttribute(mma_gemm_kernel<true>,
                         cudaFuncAttributeMaxDynamicSharedMemorySize, SMEM_MMA);
    cudaFuncSetAttribute(mma_gemm_kernel<false>,
                         cudaFuncAttributeMaxDynamicSharedMemorySize, SMEM_MMA);
    cudaFuncSetAttribute(scores_mma_kernel,
                         cudaFuncAttributeMaxDynamicSharedMemorySize, SMEM_MMA);
    cudaFuncSetAttribute(av_mma_kernel,
                         cudaFuncAttributeMaxDynamicSharedMemorySize, SMEM_AV);
    cudaGetSymbolAddress((void**)&pq, g_q);  // last: guards re-entry
  }

  ln_split_kernel<<<RX, 128>>>(x, lxg, lxb, pxnh, pxnl);
  ln_split_kernel<<<RY, 128>>>(y, lyg, lyb, pynh, pynl);
  wtrans_kernel<<<dim3(8, 8), 256>>>(Wq, pwqh, pwql);
  wtrans_kernel<<<dim3(8, 8), 256>>>(Wk, pwkh, pwkl);
  wtrans_kernel<<<dim3(8, 8), 256>>>(Wv, pwvh, pwvl);
  split_kernel<false><<<C_ * C_ / 1024, 256>>>(Wc, nullptr, pwch, pwcl);

  dim3 gg(C_ / 128, RX / 128);
  mma_gemm_kernel<true><<<gg, 256, SMEM_MMA>>>(pxnh, pxnl, pwqh, pwql, bq, pq,
                                               pqh, pql, 0.125f);
  mma_gemm_kernel<true><<<gg, 256, SMEM_MMA>>>(pynh, pynl, pwkh, pwkl, bk, pk,
                                               pkh, pkl, 1.0f);
  mma_gemm_kernel<false><<<gg, 256, SMEM_MMA>>>(pynh, pynl, pwvh, pwvl, bv, pv,
                                                nullptr, nullptr, 0.f);
  vtrans_kernel<<<dim3(M_ / 64, B_ * H_), 256>>>();

  scores_mma_kernel<<<dim3(M_ / 128, N_ / 128, B_ * H_), 256, SMEM_MMA>>>();
  stats_kernel<<<B_ * H_ * N_, 256>>>();
  renorm_kernel<<<(unsigned)((size_t)B_ * N_ * (M_ / 4) / 256), 256>>>();
  av_mma_kernel<<<dim3(N_ / 128, B_ * H_), 256, SMEM_AV>>>();

  split_kernel<true><<<(unsigned)((size_t)RX * C_ / 1024), 256>>>(pq, po, pdh, pdl);
  mma_gemm_kernel<false><<<gg, 256, SMEM_MMA>>>(pdh, pdl, pwch, pwcl, bc, ph,
                                                nullptr, nullptr, 0.f);
  final_kernel<<<RX, 128>>>(log_, lob, out);
}

// round 7
// speedup vs baseline: 2.7031x; 1.7725x over previous
#include <cuda_runtime.h>
#include <cuda_bf16.h>
#include <cuda_fp16.h>
#include <cstdint>
#include <math.h>

using bf16 = __nv_bfloat16;

namespace {
constexpr int B_  = 8;
constexpr int N_  = 2048;
constexpr int M_  = 2048;
constexpr int C_  = 512;
constexpr int H_  = 8;
constexpr int DK_ = 64;
constexpr int RX = B_ * N_;
constexpr int RY = B_ * M_;
constexpr int SMEM_MMA = 65536;   // 4 tiles of 128x64 bf16
constexpr int AV_STAGE = 24576;   // 128x64 W + 64x64 V fp16
constexpr int SMEM_AV  = 2 * AV_STAGE;
}

// ------------------------- scratch (device globals) -------------------------
__device__ float g_q [(size_t)RX * C_];
__device__ float g_k [(size_t)RY * C_];
__device__ float g_v [(size_t)RY * C_];
__device__ float g_o [(size_t)RX * C_];
__device__ float g_h [(size_t)RX * C_];
__device__ float g_sum[B_ * H_ * N_];                    // softmax row sums
__device__ __half g_e [(size_t)B_ * H_ * N_ * M_];       // exp(scores) fp16
__device__ __half g_w [(size_t)B_ * H_ * N_ * M_];       // renormed weights fp16
// bf16 hi/lo split operands
__device__ bf16 g_xnh[(size_t)RX * C_], g_xnl[(size_t)RX * C_];
__device__ bf16 g_ynh[(size_t)RY * C_], g_ynl[(size_t)RY * C_];
__device__ bf16 g_qh [(size_t)RX * C_], g_ql [(size_t)RX * C_];   // scaled 1/8
__device__ bf16 g_kh [(size_t)RY * C_], g_kl [(size_t)RY * C_];
__device__ __half g_vt [(size_t)B_ * H_ * DK_ * M_];     // V^T fp16
__device__ bf16 g_dh [(size_t)RX * C_], g_dl [(size_t)RX * C_];   // q - o
__device__ bf16 g_wqh[C_ * C_], g_wql[C_ * C_];
__device__ bf16 g_wkh[C_ * C_], g_wkl[C_ * C_];
__device__ bf16 g_wvh[C_ * C_], g_wvl[C_ * C_];
__device__ bf16 g_wch[C_ * C_], g_wcl[C_ * C_];

// ------------------------------- helpers ------------------------------------
__device__ __forceinline__ uint32_t smem_u32(const void* p) {
  uint32_t a;
  asm("{ .reg .u64 t; cvta.to.shared.u64 t, %1; cvt.u32.u64 %0, t; }"
      : "=r"(a) : "l"(p));
  return a;
}
__device__ __forceinline__ uint32_t swz(uint32_t off) {
  return off ^ ((off >> 3) & 0x70);
}
__device__ __forceinline__ void ldmat4(uint32_t* r, uint32_t addr) {
  asm volatile("ldmatrix.sync.aligned.m8n8.x4.shared.b16 {%0,%1,%2,%3}, [%4];"
               : "=r"(r[0]), "=r"(r[1]), "=r"(r[2]), "=r"(r[3]) : "r"(addr));
}
__device__ __forceinline__ void mma16816(float* c, const uint32_t* a,
                                         const uint32_t* b) {
  asm volatile(
      "mma.sync.aligned.m16n8k16.row.col.f32.bf16.bf16.f32 "
      "{%0,%1,%2,%3}, {%4,%5,%6,%7}, {%8,%9}, {%0,%1,%2,%3};"
      : "+f"(c[0]), "+f"(c[1]), "+f"(c[2]), "+f"(c[3])
      : "r"(a[0]), "r"(a[1]), "r"(a[2]), "r"(a[3]), "r"(b[0]), "r"(b[1]));
}
__device__ __forceinline__ void mma16816h(float* c, const uint32_t* a,
                                          const uint32_t* b) {
  asm volatile(
      "mma.sync.aligned.m16n8k16.row.col.f32.f16.f16.f32 "
      "{%0,%1,%2,%3}, {%4,%5,%6,%7}, {%8,%9}, {%0,%1,%2,%3};"
      : "+f"(c[0]), "+f"(c[1]), "+f"(c[2]), "+f"(c[3])
      : "r"(a[0]), "r"(a[1]), "r"(a[2]), "r"(a[3]), "r"(b[0]), "r"(b[1]));
}
__device__ __forceinline__ void split2(float a, float b, uint32_t& hi, uint32_t& lo) {
  bf16 ha = __float2bfloat16(a), hb = __float2bfloat16(b);
  float ra = a - __bfloat162float(ha);
  float rb = b - __bfloat162float(hb);
  bf16 la = __float2bfloat16(ra), lb = __float2bfloat16(rb);
  hi = (uint32_t)__bfloat16_as_ushort(ha) | ((uint32_t)__bfloat16_as_ushort(hb) << 16);
  lo = (uint32_t)__bfloat16_as_ushort(la) | ((uint32_t)__bfloat16_as_ushort(lb) << 16);
}
// load NROWS x 64 elems (16-bit) tile (row-major, stride elems) -> SW128 SMEM
template <int NROWS, typename T>
__device__ __forceinline__ void load_tile(char* smem, uint32_t sbase,
                                          const T* __restrict__ g,
                                          size_t stride, int tid) {
#pragma unroll
  for (int p = 0; p < NROWS * 8 / 256; p++) {
    const int slot = tid + p * 256;
    const int r = slot >> 3, c = slot & 7;
    const uint32_t bo = (uint32_t)(r * 128 + c * 16);
    uint4 v = *(const uint4*)(g + (size_t)r * stride + c * 8);
    *(uint4*)(smem + sbase + swz(bo)) = v;
  }
}
template <int NROWS, typename T>
__device__ __forceinline__ void load_tile_async(uint32_t sbase,
                                                const T* __restrict__ g,
                                                size_t stride, int tid) {
#pragma unroll
  for (int p = 0; p < NROWS * 8 / 256; p++) {
    const int slot = tid + p * 256;
    const int r = slot >> 3, c = slot & 7;
    const uint32_t bo = (uint32_t)(r * 128 + c * 16);
    const uint32_t dst = sbase + swz(bo);
    const void* src = g + (size_t)r * stride + c * 8;
    asm volatile("cp.async.cg.shared.global [%0], [%1], 16;"
                 :: "r"(dst), "l"(src));
  }
}

// ------------------------------- LayerNorm ----------------------------------
__global__ void __launch_bounds__(128) ln_split_kernel(
    const float* __restrict__ x, const float* __restrict__ gam,
    const float* __restrict__ bet, bf16* __restrict__ oh, bf16* __restrict__ ol) {
  const int row = blockIdx.x;
  const int t = threadIdx.x;
  float4 v = ((const float4*)(x + (size_t)row * C_))[t];
  float s  = v.x + v.y + v.z + v.w;
  float s2 = v.x * v.x + v.y * v.y + v.z * v.z + v.w * v.w;
#pragma unroll
  for (int o = 16; o > 0; o >>= 1) {
    s  += __shfl_xor_sync(0xffffffffu, s, o);
    s2 += __shfl_xor_sync(0xffffffffu, s2, o);
  }
  __shared__ float sa[4], sb[4];
  const int w = t >> 5;
  if ((t & 31) == 0) { sa[w] = s; sb[w] = s2; }
  __syncthreads();
  s  = sa[0] + sa[1] + sa[2] + sa[3];
  s2 = sb[0] + sb[1] + sb[2] + sb[3];
  const float mean = s * (1.f / C_);
  const float var  = s2 * (1.f / C_) - mean * mean;
  const float r = rsqrtf(var + 1e-5f);
  float4 gg = ((const float4*)gam)[t];
  float4 bb = ((const float4*)bet)[t];
  float ox = (v.x - mean) * r * gg.x + bb.x;
  float oy = (v.y - mean) * r * gg.y + bb.y;
  float oz = (v.z - mean) * r * gg.z + bb.z;
  float ow = (v.w - mean) * r * gg.w + bb.w;
  uint32_t h0, l0, h1, l1;
  split2(ox, oy, h0, l0);
  split2(oz, ow, h1, l1);
  const size_t off = (size_t)row * C_ + t * 4;
  uint2 hh = {h0, h1}, ll = {l0, l1};
  *(uint2*)(oh + off) = hh;
  *(uint2*)(ol + off) = ll;
}

// ------------------- weight transpose + split (Wq/Wk/Wv) --------------------
__global__ void __launch_bounds__(256) wtrans_kernel(
    const float* __restrict__ W, bf16* __restrict__ th, bf16* __restrict__ tl) {
  __shared__ float t[64][65];
  const int c0 = blockIdx.y * 64, j0 = blockIdx.x * 64;
  const int tid = threadIdx.x;
#pragma unroll
  for (int p = 0; p < 4; p++) {
    const int slot = tid + p * 256;
    const int r = slot >> 4, c4 = slot & 15;
    float4 v = *(const float4*)(W + (size_t)(c0 + r) * C_ + j0 + c4 * 4);
    t[r][c4 * 4 + 0] = v.x; t[r][c4 * 4 + 1] = v.y;
    t[r][c4 * 4 + 2] = v.z; t[r][c4 * 4 + 3] = v.w;
  }
  __syncthreads();
#pragma unroll
  for (int p = 0; p < 4; p++) {
    const int slot = tid + p * 256;
    const int jr = slot >> 4, c4 = slot & 15;
    float v0 = t[c4 * 4 + 0][jr], v1 = t[c4 * 4 + 1][jr];
    float v2 = t[c4 * 4 + 2][jr], v3 = t[c4 * 4 + 3][jr];
    uint32_t h0, l0, h1, l1;
    split2(v0, v1, h0, l0);
    split2(v2, v3, h1, l1);
    const size_t off = (size_t)(j0 + jr) * C_ + c0 + c4 * 4;
    uint2 hh = {h0, h1}, ll = {l0, l1};
    *(uint2*)(th + off) = hh;
    *(uint2*)(tl + off) = ll;
  }
}

// ------------------- elementwise split (Wc and q-o diff) --------------------
template <bool SUB>
__global__ void __launch_bounds__(256) split_kernel(
    const float* __restrict__ a, const float* __restrict__ b,
    bf16* __restrict__ oh, bf16* __restrict__ ol) {
  const size_t i4 = (size_t)blockIdx.x * 256 + threadIdx.x;
  float4 v = ((const float4*)a)[i4];
  if (SUB) {
    float4 w = ((const float4*)b)[i4];
    v.x -= w.x; v.y -= w.y; v.z -= w.z; v.w -= w.w;
  }
  uint32_t h0, l0, h1, l1;
  split2(v.x, v.y, h0, l0);
  split2(v.z, v.w, h1, l1);
  uint2 hh = {h0, h1}, ll = {l0, l1};
  *(uint2*)(oh + i4 * 4) = hh;
  *(uint2*)(ol + i4 * 4) = ll;
}

// ---------------------- zero softmax row-sum accumulator --------------------
__global__ void __launch_bounds__(256) zero_sum_kernel() {
  g_sum[blockIdx.x * 256 + threadIdx.x] = 0.f;
}

// --------------------- V transpose to [bh][d][m] fp16 -----------------------
__global__ void __launch_bounds__(256) vtrans_kernel() {
  __shared__ float t[64][65];
  const int bh = blockIdx.y;
  const int b = bh >> 3, h = bh & 7;
  const int m0 = blockIdx.x * 64;
  const int tid = threadIdx.x;
#pragma unroll
  for (int p = 0; p < 4; p++) {
    const int slot = tid + p * 256;
    const int r = slot >> 4, c4 = slot & 15;
    float4 v = *(const float4*)(g_v + (size_t)(b * M_ + m0 + r) * C_ + h * DK_ + c4 * 4);
    t[r][c4 * 4 + 0] = v.x; t[r][c4 * 4 + 1] = v.y;
    t[r][c4 * 4 + 2] = v.z; t[r][c4 * 4 + 3] = v.w;
  }
  __syncthreads();
#pragma unroll
  for (int p = 0; p < 4; p++) {
    const int slot = tid + p * 256;
    const int d = slot >> 4, c4 = slot & 15;
    __half b0 = __float2half_rn(t[c4 * 4 + 0][d]);
    __half b1 = __float2half_rn(t[c4 * 4 + 1][d]);
    __half b2 = __float2half_rn(t[c4 * 4 + 2][d]);
    __half b3 = __float2half_rn(t[c4 * 4 + 3][d]);
    uint32_t w0 = (uint32_t)__half_as_ushort(b0) |
                  ((uint32_t)__half_as_ushort(b1) << 16);
    uint32_t w1 = (uint32_t)__half_as_ushort(b2) |
                  ((uint32_t)__half_as_ushort(b3) << 16);
    const size_t off = ((size_t)bh * DK_ + d) * M_ + m0 + c4 * 4;
    uint2 ww = {w0, w1};
    *(uint2*)(g_vt + off) = ww;
  }
}

// ---------------- dense HMMA GEMM: out[16384,512] = A·Bt + bias -------------
template <bool WRITE_SPLIT>
__global__ void __launch_bounds__(256) mma_gemm_kernel(
    const bf16* __restrict__ Ahi, const bf16* __restrict__ Alo,
    const bf16* __restrict__ Bhi, const bf16* __restrict__ Blo,
    const float* __restrict__ bias, float* __restrict__ out,
    bf16* __restrict__ ohi, bf16* __restrict__ olo, float oscale) {
  extern __shared__ __align__(128) char smem[];
  const uint32_t sbase = smem_u32(smem);
  const int tid = threadIdx.x, wid = tid >> 5, lane = tid & 31;
  const int bm = blockIdx.y * 128, bn = blockIdx.x * 128;
  constexpr uint32_t AH = 0, AL = 16384, BH = 32768, BL = 49152;
  const int mw = (wid & 1) * 64, nw = (wid >> 1) * 32;
  const int arow = (lane & 7) + (lane & 8);
  const uint32_t akb = (uint32_t)(lane & 16);
  const int brow = (lane & 7) + ((lane & 16) >> 1);
  const uint32_t bkb = (uint32_t)((lane & 8) * 2);
  float acc[4][4][4] = {};
  for (int kb = 0; kb < 8; kb++) {
    const int k0 = kb * 64;
    __syncthreads();
    load_tile<128>(smem, AH, Ahi + (size_t)bm * C_ + k0, C_, tid);
    load_tile<128>(smem, AL, Alo + (size_t)bm * C_ + k0, C_, tid);
    load_tile<128>(smem, BH, Bhi + (size_t)bn * C_ + k0, C_, tid);
    load_tile<128>(smem, BL, Blo + (size_t)bn * C_ + k0, C_, tid);
    __syncthreads();
#pragma unroll
    for (int ks = 0; ks < 4; ks++) {
      uint32_t ah[4][4], al[4][4], bh[4][2], bl[4][2];
#pragma unroll
      for (int mt = 0; mt < 4; mt++) {
        const uint32_t off = (uint32_t)((mw + mt * 16 + arow) * 128) + ks * 32 + akb;
        ldmat4(ah[mt], sbase + AH + swz(off));
        ldmat4(al[mt], sbase + AL + swz(off));
      }
#pragma unroll
      for (int np = 0; np < 2; np++) {
        const uint32_t off = (uint32_t)((nw + np * 16 + brow) * 128) + ks * 32 + bkb;
        uint32_t t4[4];
        ldmat4(t4, sbase + BH + swz(off));
        bh[np * 2][0] = t4[0]; bh[np * 2][1] = t4[1];
        bh[np * 2 + 1][0] = t4[2]; bh[np * 2 + 1][1] = t4[3];
        ldmat4(t4, sbase + BL + swz(off));
        bl[np * 2][0] = t4[0]; bl[np * 2][1] = t4[1];
        bl[np * 2 + 1][0] = t4[2]; bl[np * 2 + 1][1] = t4[3];
      }
#pragma unroll
      for (int mt = 0; mt < 4; mt++)
#pragma unroll
        for (int nt = 0; nt < 4; nt++) {
          mma16816(acc[mt][nt], ah[mt], bh[nt]);
          mma16816(acc[mt][nt], ah[mt], bl[nt]);
          mma16816(acc[mt][nt], al[mt], bh[nt]);
        }
    }
  }
  const int rbase = bm + mw + (lane >> 2);
  const int cbase = bn + nw + (lane & 3) * 2;
#pragma unroll
  for (int mt = 0; mt < 4; mt++)
#pragma unroll
    for (int nt = 0; nt < 4; nt++) {
      const int c = cbase + nt * 8;
      const float b0v = bias[c], b1v = bias[c + 1];
#pragma unroll
      for (int hr = 0; hr < 2; hr++) {
        const int r = rbase + mt * 16 + hr * 8;
        const float v0 = acc[mt][nt][hr * 2] + b0v;
        const float v1 = acc[mt][nt][hr * 2 + 1] + b1v;
        float2 o2 = {v0, v1};
        *(float2*)(out + (size_t)r * C_ + c) = o2;
        if (WRITE_SPLIT) {
          uint32_t hw, lw;
          split2(v0 * oscale, v1 * oscale, hw, lw);
          *(uint32_t*)(ohi + (size_t)r * C_ + c) = hw;
          *(uint32_t*)(olo + (size_t)r * C_ + c) = lw;
        }
      }
    }
}

// ------- scores fused: e = exp((q/8)·k) -> fp16, row sums via atomics -------
__global__ void __launch_bounds__(256) scores_mma_kernel() {
  extern __shared__ __align__(128) char smem[];
  const uint32_t sbase = smem_u32(smem);
  const int tid = threadIdx.x, wid = tid >> 5, lane = tid & 31;
  const int bhz = blockIdx.z, b = bhz >> 3, h = bhz & 7;
  const int n0 = blockIdx.y << 7, m0 = blockIdx.x << 7;
  constexpr uint32_t AH = 0, AL = 16384, BH = 32768, BL = 49152;
  const int mw = (wid & 1) * 64, nw = (wid >> 1) * 32;
  const int arow = (lane & 7) + (lane & 8);
  const uint32_t akb = (uint32_t)(lane & 16);
  const int brow = (lane & 7) + ((lane & 16) >> 1);
  const uint32_t bkb = (uint32_t)((lane & 8) * 2);
  const size_t qoff = (size_t)(b * N_ + n0) * C_ + h * DK_;
  const size_t koff = (size_t)(b * M_ + m0) * C_ + h * DK_;
  load_tile<128>(smem, AH, g_qh + qoff, C_, tid);
  load_tile<128>(smem, AL, g_ql + qoff, C_, tid);
  load_tile<128>(smem, BH, g_kh + koff, C_, tid);
  load_tile<128>(smem, BL, g_kl + koff, C_, tid);
  __syncthreads();
  float acc[4][4][4] = {};
#pragma unroll
  for (int ks = 0; ks < 4; ks++) {
    uint32_t ah[4][4], al[4][4], bh[4][2], bl[4][2];
#pragma unroll
    for (int mt = 0; mt < 4; mt++) {
      const uint32_t off = (uint32_t)((mw + mt * 16 + arow) * 128) + ks * 32 + akb;
      ldmat4(ah[mt], sbase + AH + swz(off));
      ldmat4(al[mt], sbase + AL + swz(off));
    }
#pragma unroll
    for (int np = 0; np < 2; np++) {
      const uint32_t off = (uint32_t)((nw + np * 16 + brow) * 128) + ks * 32 + bkb;
      uint32_t t4[4];
      ldmat4(t4, sbase + BH + swz(off));
      bh[np * 2][0] = t4[0]; bh[np * 2][1] = t4[1];
      bh[np * 2 + 1][0] = t4[2]; bh[np * 2 + 1][1] = t4[3];
      ldmat4(t4, sbase + BL + swz(off));
      bl[np * 2][0] = t4[0]; bl[np * 2][1] = t4[1];
      bl[np * 2 + 1][0] = t4[2]; bl[np * 2 + 1][1] = t4[3];
    }
#pragma unroll
    for (int mt = 0; mt < 4; mt++)
#pragma unroll
      for (int nt = 0; nt < 4; nt++) {
        mma16816(acc[mt][nt], ah[mt], bh[nt]);
        mma16816(acc[mt][nt], ah[mt], bl[nt]);
        mma16816(acc[mt][nt], al[mt], bh[nt]);
      }
  }
  // epilogue: e = exp(s) (|s| small: no max-shift), fp16 store + row sums
  const int rbase = n0 + mw + (lane >> 2);
  const int cbase = m0 + nw + (lane & 3) * 2;
  __half* ep = g_e + (size_t)bhz * N_ * M_;
  float* rowsum = g_sum + (size_t)bhz * N_;
#pragma unroll
  for (int mt = 0; mt < 4; mt++) {
#pragma unroll
    for (int hr = 0; hr < 2; hr++) {
      const int r = rbase + mt * 16 + hr * 8;
      float ps = 0.f;
#pragma unroll
      for (int nt = 0; nt < 4; nt++) {
        const float e0 = __expf(acc[mt][nt][hr * 2]);
        const float e1 = __expf(acc[mt][nt][hr * 2 + 1]);
        ps += e0 + e1;
        __half eb0 = __float2half_rn(e0), eb1 = __float2half_rn(e1);
        uint32_t ew = (uint32_t)__half_as_ushort(eb0) |
                      ((uint32_t)__half_as_ushort(eb1) << 16);
        *(uint32_t*)(ep + (size_t)r * M_ + cbase + nt * 8) = ew;
      }
      ps += __shfl_xor_sync(0xffffffffu, ps, 1);
      ps += __shfl_xor_sync(0xffffffffu, ps, 2);
      if ((lane & 3) == 0) atomicAdd(rowsum + r, ps);
    }
  }
}

// ---------------- cross-head renorm -> fp16 weights -------------------------
__global__ void __launch_bounds__(256) renorm_kernel() {
  const size_t idx = (size_t)blockIdx.x * 256 + threadIdx.x;
  const int m4 = (int)(idx & (M_ / 4 - 1));
  const size_t bn = idx >> 9;
  const int n = (int)(bn & (N_ - 1));
  const int b = (int)(bn >> 11);
  float4 p[8];
  size_t off[8];
  float dx = 1e-9f, dy = 1e-9f, dz = 1e-9f, dw = 1e-9f;
#pragma unroll
  for (int h = 0; h < 8; h++) {
    const size_t row = (size_t)(b * H_ + h) * N_ + n;
    const size_t o = row * M_ + (size_t)m4 * 4;
    off[h] = o;
    uint2 ee = *(const uint2*)(g_e + o);
    const float rl = 1.f / g_sum[row];
    float4 pv;
    pv.x = __half2float(__ushort_as_half((unsigned short)(ee.x & 0xffff))) * rl;
    pv.y = __half2float(__ushort_as_half((unsigned short)(ee.x >> 16))) * rl;
    pv.z = __half2float(__ushort_as_half((unsigned short)(ee.y & 0xffff))) * rl;
    pv.w = __half2float(__ushort_as_half((unsigned short)(ee.y >> 16))) * rl;
    p[h] = pv;
    dx += pv.x; dy += pv.y; dz += pv.z; dw += pv.w;
  }
  const float ix = 1.f / dx, iy = 1.f / dy, iz = 1.f / dz, iw = 1.f / dw;
#pragma unroll
  for (int h = 0; h < 8; h++) {
    __half w0 = __float2half_rn(p[h].x * ix);
    __half w1 = __float2half_rn(p[h].y * iy);
    __half w2 = __float2half_rn(p[h].z * iz);
    __half w3 = __float2half_rn(p[h].w * iw);
    uint2 ww;
    ww.x = (uint32_t)__half_as_ushort(w0) | ((uint32_t)__half_as_ushort(w1) << 16);
    ww.y = (uint32_t)__half_as_ushort(w2) | ((uint32_t)__half_as_ushort(w3) << 16);
    *(uint2*)(g_w + off[h]) = ww;
  }
}

// ------- AV: O[n,d] = W·Vt per (b,h), fp16 single-MMA, cp.async 2-stage -----
__global__ void __launch_bounds__(256) av_mma_kernel() {
  extern __shared__ __align__(128) char smem[];
  const uint32_t sbase = smem_u32(smem);
  const int tid = threadIdx.x, wid = tid >> 5, lane = tid & 31;
  const int bhz = blockIdx.y, b = bhz >> 3, h = bhz & 7;
  const int n0 = blockIdx.x << 7;
  const int mw = (wid & 3) * 32, nw = (wid >> 2) * 32;
  const int arow = (lane & 7) + (lane & 8);
  const uint32_t akb = (uint32_t)(lane & 16);
  const int brow = (lane & 7) + ((lane & 16) >> 1);
  const uint32_t bkb = (uint32_t)((lane & 8) * 2);
  const size_t wbase = ((size_t)bhz * N_ + n0) * M_;
  const size_t vbase = (size_t)bhz * DK_ * M_;
  float acc[2][4][4] = {};
  load_tile_async<128>(sbase, g_w + wbase, M_, tid);
  load_tile_async<64>(sbase + 16384, g_vt + vbase, M_, tid);
  asm volatile("cp.async.commit_group;" ::: "memory");
  for (int kb = 0; kb < 32; kb++) {
    if (kb < 31) {
      const uint32_t st = (uint32_t)((kb + 1) & 1) * AV_STAGE;
      load_tile_async<128>(sbase + st, g_w + wbase + (kb + 1) * 64, M_, tid);
      load_tile_async<64>(sbase + st + 16384, g_vt + vbase + (kb + 1) * 64, M_, tid);
      asm volatile("cp.async.commit_group;" ::: "memory");
      asm volatile("cp.async.wait_group 1;" ::: "memory");
    } else {
      asm volatile("cp.async.wait_group 0;" ::: "memory");
    }
    __syncthreads();
    const uint32_t cs = (uint32_t)(kb & 1) * AV_STAGE;
#pragma unroll
    for (int ks = 0; ks < 4; ks++) {
      uint32_t ah[2][4], bh[4][2];
#pragma unroll
      for (int mt = 0; mt < 2; mt++) {
        const uint32_t off = (uint32_t)((mw + mt * 16 + arow) * 128) + ks * 32 + akb;
        ldmat4(ah[mt], sbase + cs + swz(off));
      }
#pragma unroll
      for (int np = 0; np < 2; np++) {
        const uint32_t off = (uint32_t)((nw + np * 16 + brow) * 128) + ks * 32 + bkb;
        uint32_t t4[4];
        ldmat4(t4, sbase + cs + 16384 + swz(off));
        bh[np * 2][0] = t4[0]; bh[np * 2][1] = t4[1];
        bh[np * 2 + 1][0] = t4[2]; bh[np * 2 + 1][1] = t4[3];
      }
#pragma unroll
      for (int mt = 0; mt < 2; mt++)
#pragma unroll
        for (int nt = 0; nt < 4; nt++)
          mma16816h(acc[mt][nt], ah[mt], bh[nt]);
    }
    __syncthreads();
  }
  const int rbase = n0 + mw + (lane >> 2);
  const int cbase = nw + (lane & 3) * 2;
#pragma unroll
  for (int mt = 0; mt < 2; mt++)
#pragma unroll
    for (int nt = 0; nt < 4; nt++) {
#pragma unroll
      for (int hr = 0; hr < 2; hr++) {
        const int r = rbase + mt * 16 + hr * 8;
        const int c = cbase + nt * 8;
        float2 o2 = {acc[mt][nt][hr * 2], acc[mt][nt][hr * 2 + 1]};
        *(float2*)(g_o + (size_t)(b * N_ + r) * C_ + h * DK_ + c) = o2;
      }
    }
}

// --------------------- final: out = q + leaky_relu(LN(h)) -------------------
__global__ void __launch_bounds__(128) final_kernel(
    const float* __restrict__ gam, const float* __restrict__ bet,
    float* __restrict__ out) {
  const int row = blockIdx.x;
  const int t = threadIdx.x;
  float4 v = ((const float4*)(g_h + (size_t)row * C_))[t];
  float s  = v.x + v.y + v.z + v.w;
  float s2 = v.x * v.x + v.y * v.y + v.z * v.z + v.w * v.w;
#pragma unroll
  for (int o = 16; o > 0; o >>= 1) {
    s  += __shfl_xor_sync(0xffffffffu, s, o);
    s2 += __shfl_xor_sync(0xffffffffu, s2, o);
  }
  __shared__ float sa[4], sb[4];
  const int w = t >> 5;
  if ((t & 31) == 0) { sa[w] = s; sb[w] = s2; }
  __syncthreads();
  s  = sa[0] + sa[1] + sa[2] + sa[3];
  s2 = sb[0] + sb[1] + sb[2] + sb[3];
  const float mean = s * (1.f / C_);
  const float var  = s2 * (1.f / C_) - mean * mean;
  const float r = rsqrtf(var + 1e-5f);
  float4 gg = ((const float4*)gam)[t];
  float4 bb = ((const float4*)bet)[t];
  float4 q4 = ((const float4*)(g_q + (size_t)row * C_))[t];
  float4 o;
  float y;
  y = (v.x - mean) * r * gg.x + bb.x; y = y > 0.f ? y : 0.02f * y; o.x = q4.x + y;
  y = (v.y - mean) * r * gg.y + bb.y; y = y > 0.f ? y : 0.02f * y; o.y = q4.y + y;
  y = (v.z - mean) * r * gg.z + bb.z; y = y > 0.f ? y : 0.02f * y; o.z = q4.z + y;
  y = (v.w - mean) * r * gg.w + bb.w; y = y > 0.f ? y : 0.02f * y; o.w = q4.w + y;
  ((float4*)(out + (size_t)row * C_))[t] = o;
}

// ---------------------------------------------------------------------------
extern "C" void kernel_launch(void* const* d_in, const int* in_sizes, int n_in,
                              void* d_out, int out_size) {
  (void)in_sizes; (void)n_in; (void)out_size;
  const float* x   = (const float*)d_in[0];
  const float* y   = (const float*)d_in[1];
  const float* lxg = (const float*)d_in[2];
  const float* lxb = (const float*)d_in[3];
  const float* lyg = (const float*)d_in[4];
  const float* lyb = (const float*)d_in[5];
  const float* Wq  = (const float*)d_in[6];
  const float* bq  = (const float*)d_in[7];
  const float* Wk  = (const float*)d_in[8];
  const float* bk  = (const float*)d_in[9];
  const float* Wv  = (const float*)d_in[10];
  const float* bv  = (const float*)d_in[11];
  const float* Wc  = (const float*)d_in[12];
  const float* bc  = (const float*)d_in[13];
  const float* log_ = (const float*)d_in[14];
  const float* lob  = (const float*)d_in[15];
  float* out = (float*)d_out;

  static float *pq = nullptr, *pk, *pv, *po, *ph;
  static bf16 *pxnh, *pxnl, *pynh, *pynl, *pqh, *pql, *pkh, *pkl;
  static bf16 *pwqh, *pwql, *pwkh, *pwkl, *pwvh, *pwvl, *pwch, *pwcl, *pdh, *pdl;
  if (!pq) {
    cudaGetSymbolAddress((void**)&pk,   g_k);
    cudaGetSymbolAddress((void**)&pv,   g_v);
    cudaGetSymbolAddress((void**)&po,   g_o);
    cudaGetSymbolAddress((void**)&ph,   g_h);
    cudaGetSymbolAddress((void**)&pxnh, g_xnh);
    cudaGetSymbolAddress((void**)&pxnl, g_xnl);
    cudaGetSymbolAddress((void**)&pynh, g_ynh);
    cudaGetSymbolAddress((void**)&pynl, g_ynl);
    cudaGetSymbolAddress((void**)&pqh,  g_qh);
    cudaGetSymbolAddress((void**)&pql,  g_ql);
    cudaGetSymbolAddress((void**)&pkh,  g_kh);
    cudaGetSymbolAddress((void**)&pkl,  g_kl);
    cudaGetSymbolAddress((void**)&pwqh, g_wqh);
    cudaGetSymbolAddress((void**)&pwql, g_wql);
    cudaGetSymbolAddress((void**)&pwkh, g_wkh);
    cudaGetSymbolAddress((void**)&pwkl, g_wkl);
    cudaGetSymbolAddress((void**)&pwvh, g_wvh);
    cudaGetSymbolAddress((void**)&pwvl, g_wvl);
    cudaGetSymbolAddress((void**)&pwch, g_wch);
    cudaGetSymbolAddress((void**)&pwcl, g_wcl);
    cudaGetSymbolAddress((void**)&pdh,  g_dh);
    cudaGetSymbolAddress((void**)&pdl,  g_dl);
    cudaFuncSetAttribute(mma_gemm_kernel<true>,
                         cudaFuncAttributeMaxDynamicSharedMemorySize, SMEM_MMA);
    cudaFuncSetAttribute(mma_gemm_kernel<false>,
                         cudaFuncAttributeMaxDynamicSharedMemorySize, SMEM_MMA);
    cudaFuncSetAttribute(scores_mma_kernel,
                         cudaFuncAttributeMaxDynamicSharedMemorySize, SMEM_MMA);
    cudaFuncSetAttribute(av_mma_kernel,
                         cudaFuncAttributeMaxDynamicSharedMemorySize, SMEM_AV);
    cudaGetSymbolAddress((void**)&pq, g_q);  // last: guards re-entry
  }

  ln_split_kernel<<<RX, 128>>>(x, lxg, lxb, pxnh, pxnl);
  ln_split_kernel<<<RY, 128>>>(y, lyg, lyb, pynh, pynl);
  wtrans_kernel<<<dim3(8, 8), 256>>>(Wq, pwqh, pwql);
  wtrans_kernel<<<dim3(8, 8), 256>>>(Wk, pwkh, pwkl);
  wtrans_kernel<<<dim3(8, 8), 256>>>(Wv, pwvh, pwvl);
  split_kernel<false><<<C_ * C_ / 1024, 256>>>(Wc, nullptr, pwch, pwcl);
  zero_sum_kernel<<<B_ * H_ * N_ / 256, 256>>>();

  dim3 gg(C_ / 128, RX / 128);
  mma_gemm_kernel<true><<<gg, 256, SMEM_MMA>>>(pxnh, pxnl, pwqh, pwql, bq, pq,
                                               pqh, pql, 0.125f);
  mma_gemm_kernel<true><<<gg, 256, SMEM_MMA>>>(pynh, pynl, pwkh, pwkl, bk, pk,
                                               pkh, pkl, 1.0f);
  mma_gemm_kernel<false><<<gg, 256, SMEM_MMA>>>(pynh, pynl, pwvh, pwvl, bv, pv,
                                                nullptr, nullptr, 0.f);
  vtrans_kernel<<<dim3(M_ / 64, B_ * H_), 256>>>();

  scores_mma_kernel<<<dim3(M_ / 128, N_ / 128, B_ * H_), 256, SMEM_MMA>>>();
  renorm_kernel<<<(unsigned)((size_t)B_ * N_ * (M_ / 4) / 256), 256>>>();
  av_mma_kernel<<<dim3(N_ / 128, B_ * H_), 256, SMEM_AV>>>();

  split_kernel<true><<<(unsigned)((size_t)RX * C_ / 1024), 256>>>(pq, po, pdh, pdl);
  mma_gemm_kernel<false><<<gg, 256, SMEM_MMA>>>(pdh, pdl, pwch, pwcl, bc, ph,
                                                nullptr, nullptr, 0.f);
  final_kernel<<<RX, 128>>>(log_, lob, out);
}

// round 8
// speedup vs baseline: 2.8895x; 1.0690x over previous
#include <cuda_runtime.h>
#include <cuda_bf16.h>
#include <cuda_fp16.h>
#include <cstdint>
#include <math.h>

using bf16 = __nv_bfloat16;

namespace {
constexpr int B_  = 8;
constexpr int N_  = 2048;
constexpr int M_  = 2048;
constexpr int C_  = 512;
constexpr int H_  = 8;
constexpr int DK_ = 64;
constexpr int RX = B_ * N_;
constexpr int RY = B_ * M_;
constexpr int SMEM_MMA = 65536;     // 4 tiles of 128x64 bf16
constexpr int AVF_STAGE = 98304;    // 8 e-tiles (32x64) + 8 V-tiles (64x64) fp16
constexpr int SMEM_AVF  = 1024 + 2 * AVF_STAGE;  // rl + 2 stages = 197632
}

// ------------------------- scratch (device globals) -------------------------
__device__ float g_q [(size_t)RX * C_];
__device__ float g_v [(size_t)RY * C_];
__device__ float g_h [(size_t)RX * C_];
__device__ float g_sum[B_ * H_ * N_];                    // softmax row sums
__device__ __half g_e [(size_t)B_ * H_ * N_ * M_];       // exp(scores) fp16
// bf16 hi/lo split operands
__device__ bf16 g_xnh[(size_t)RX * C_], g_xnl[(size_t)RX * C_];
__device__ bf16 g_ynh[(size_t)RY * C_], g_ynl[(size_t)RY * C_];
__device__ bf16 g_qh [(size_t)RX * C_], g_ql [(size_t)RX * C_];   // scaled 1/8
__device__ bf16 g_kh [(size_t)RY * C_], g_kl [(size_t)RY * C_];
__device__ __half g_vt [(size_t)B_ * H_ * DK_ * M_];     // V^T fp16
__device__ bf16 g_dh [(size_t)RX * C_], g_dl [(size_t)RX * C_];   // q - o
__device__ bf16 g_wqh[C_ * C_], g_wql[C_ * C_];
__device__ bf16 g_wkh[C_ * C_], g_wkl[C_ * C_];
__device__ bf16 g_wvh[C_ * C_], g_wvl[C_ * C_];
__device__ bf16 g_wch[C_ * C_], g_wcl[C_ * C_];

// ------------------------------- helpers ------------------------------------
__device__ __forceinline__ uint32_t smem_u32(const void* p) {
  uint32_t a;
  asm("{ .reg .u64 t; cvta.to.shared.u64 t, %1; cvt.u32.u64 %0, t; }"
      : "=r"(a) : "l"(p));
  return a;
}
__device__ __forceinline__ uint32_t swz(uint32_t off) {
  return off ^ ((off >> 3) & 0x70);
}
__device__ __forceinline__ void ldmat4(uint32_t* r, uint32_t addr) {
  asm volatile("ldmatrix.sync.aligned.m8n8.x4.shared.b16 {%0,%1,%2,%3}, [%4];"
               : "=r"(r[0]), "=r"(r[1]), "=r"(r[2]), "=r"(r[3]) : "r"(addr));
}
__device__ __forceinline__ void mma16816(float* c, const uint32_t* a,
                                         const uint32_t* b) {
  asm volatile(
      "mma.sync.aligned.m16n8k16.row.col.f32.bf16.bf16.f32 "
      "{%0,%1,%2,%3}, {%4,%5,%6,%7}, {%8,%9}, {%0,%1,%2,%3};"
      : "+f"(c[0]), "+f"(c[1]), "+f"(c[2]), "+f"(c[3])
      : "r"(a[0]), "r"(a[1]), "r"(a[2]), "r"(a[3]), "r"(b[0]), "r"(b[1]));
}
__device__ __forceinline__ void mma16816h(float* c, const uint32_t* a,
                                          const uint32_t* b) {
  asm volatile(
      "mma.sync.aligned.m16n8k16.row.col.f32.f16.f16.f32 "
      "{%0,%1,%2,%3}, {%4,%5,%6,%7}, {%8,%9}, {%0,%1,%2,%3};"
      : "+f"(c[0]), "+f"(c[1]), "+f"(c[2]), "+f"(c[3])
      : "r"(a[0]), "r"(a[1]), "r"(a[2]), "r"(a[3]), "r"(b[0]), "r"(b[1]));
}
__device__ __forceinline__ void split2(float a, float b, uint32_t& hi, uint32_t& lo) {
  bf16 ha = __float2bfloat16(a), hb = __float2bfloat16(b);
  float ra = a - __bfloat162float(ha);
  float rb = b - __bfloat162float(hb);
  bf16 la = __float2bfloat16(ra), lb = __float2bfloat16(rb);
  hi = (uint32_t)__bfloat16_as_ushort(ha) | ((uint32_t)__bfloat16_as_ushort(hb) << 16);
  lo = (uint32_t)__bfloat16_as_ushort(la) | ((uint32_t)__bfloat16_as_ushort(lb) << 16);
}
__device__ __forceinline__ float h2f(uint32_t w, int hi) {
  return __half2float(__ushort_as_half((unsigned short)(hi ? (w >> 16) : (w & 0xffff))));
}
// load NROWS x 64 elems (16-bit) tile (row-major, stride elems) -> SW128 SMEM
template <int NROWS, typename T>
__device__ __forceinline__ void load_tile(char* smem, uint32_t sbase,
                                          const T* __restrict__ g,
                                          size_t stride, int tid) {
#pragma unroll
  for (int p = 0; p < NROWS * 8 / 256; p++) {
    const int slot = tid + p * 256;
    const int r = slot >> 3, c = slot & 7;
    const uint32_t bo = (uint32_t)(r * 128 + c * 16);
    uint4 v = *(const uint4*)(g + (size_t)r * stride + c * 8);
    *(uint4*)(smem + sbase + swz(bo)) = v;
  }
}

// ------------------------------- LayerNorm ----------------------------------
__global__ void __launch_bounds__(128) ln_split_kernel(
    const float* __restrict__ x, const float* __restrict__ gam,
    const float* __restrict__ bet, bf16* __restrict__ oh, bf16* __restrict__ ol) {
  const int row = blockIdx.x;
  const int t = threadIdx.x;
  float4 v = ((const float4*)(x + (size_t)row * C_))[t];
  float s  = v.x + v.y + v.z + v.w;
  float s2 = v.x * v.x + v.y * v.y + v.z * v.z + v.w * v.w;
#pragma unroll
  for (int o = 16; o > 0; o >>= 1) {
    s  += __shfl_xor_sync(0xffffffffu, s, o);
    s2 += __shfl_xor_sync(0xffffffffu, s2, o);
  }
  __shared__ float sa[4], sb[4];
  const int w = t >> 5;
  if ((t & 31) == 0) { sa[w] = s; sb[w] = s2; }
  __syncthreads();
  s  = sa[0] + sa[1] + sa[2] + sa[3];
  s2 = sb[0] + sb[1] + sb[2] + sb[3];
  const float mean = s * (1.f / C_);
  const float var  = s2 * (1.f / C_) - mean * mean;
  const float r = rsqrtf(var + 1e-5f);
  float4 gg = ((const float4*)gam)[t];
  float4 bb = ((const float4*)bet)[t];
  float ox = (v.x - mean) * r * gg.x + bb.x;
  float oy = (v.y - mean) * r * gg.y + bb.y;
  float oz = (v.z - mean) * r * gg.z + bb.z;
  float ow = (v.w - mean) * r * gg.w + bb.w;
  uint32_t h0, l0, h1, l1;
  split2(ox, oy, h0, l0);
  split2(oz, ow, h1, l1);
  const size_t off = (size_t)row * C_ + t * 4;
  uint2 hh = {h0, h1}, ll = {l0, l1};
  *(uint2*)(oh + off) = hh;
  *(uint2*)(ol + off) = ll;
}

// ------------------- weight transpose + split (Wq/Wk/Wv) --------------------
__global__ void __launch_bounds__(256) wtrans_kernel(
    const float* __restrict__ W, bf16* __restrict__ th, bf16* __restrict__ tl) {
  __shared__ float t[64][65];
  const int c0 = blockIdx.y * 64, j0 = blockIdx.x * 64;
  const int tid = threadIdx.x;
#pragma unroll
  for (int p = 0; p < 4; p++) {
    const int slot = tid + p * 256;
    const int r = slot >> 4, c4 = slot & 15;
    float4 v = *(const float4*)(W + (size_t)(c0 + r) * C_ + j0 + c4 * 4);
    t[r][c4 * 4 + 0] = v.x; t[r][c4 * 4 + 1] = v.y;
    t[r][c4 * 4 + 2] = v.z; t[r][c4 * 4 + 3] = v.w;
  }
  __syncthreads();
#pragma unroll
  for (int p = 0; p < 4; p++) {
    const int slot = tid + p * 256;
    const int jr = slot >> 4, c4 = slot & 15;
    float v0 = t[c4 * 4 + 0][jr], v1 = t[c4 * 4 + 1][jr];
    float v2 = t[c4 * 4 + 2][jr], v3 = t[c4 * 4 + 3][jr];
    uint32_t h0, l0, h1, l1;
    split2(v0, v1, h0, l0);
    split2(v2, v3, h1, l1);
    const size_t off = (size_t)(j0 + jr) * C_ + c0 + c4 * 4;
    uint2 hh = {h0, h1}, ll = {l0, l1};
    *(uint2*)(th + off) = hh;
    *(uint2*)(tl + off) = ll;
  }
}

// ------------------------- elementwise split (Wc) ---------------------------
__global__ void __launch_bounds__(256) split_kernel(
    const float* __restrict__ a, bf16* __restrict__ oh, bf16* __restrict__ ol) {
  const size_t i4 = (size_t)blockIdx.x * 256 + threadIdx.x;
  float4 v = ((const float4*)a)[i4];
  uint32_t h0, l0, h1, l1;
  split2(v.x, v.y, h0, l0);
  split2(v.z, v.w, h1, l1);
  uint2 hh = {h0, h1}, ll = {l0, l1};
  *(uint2*)(oh + i4 * 4) = hh;
  *(uint2*)(ol + i4 * 4) = ll;
}

// ---------------------- zero softmax row-sum accumulator --------------------
__global__ void __launch_bounds__(256) zero_sum_kernel() {
  g_sum[blockIdx.x * 256 + threadIdx.x] = 0.f;
}

// --------------------- V transpose to [bh][d][m] fp16 -----------------------
__global__ void __launch_bounds__(256) vtrans_kernel() {
  __shared__ float t[64][65];
  const int bh = blockIdx.y;
  const int b = bh >> 3, h = bh & 7;
  const int m0 = blockIdx.x * 64;
  const int tid = threadIdx.x;
#pragma unroll
  for (int p = 0; p < 4; p++) {
    const int slot = tid + p * 256;
    const int r = slot >> 4, c4 = slot & 15;
    float4 v = *(const float4*)(g_v + (size_t)(b * M_ + m0 + r) * C_ + h * DK_ + c4 * 4);
    t[r][c4 * 4 + 0] = v.x; t[r][c4 * 4 + 1] = v.y;
    t[r][c4 * 4 + 2] = v.z; t[r][c4 * 4 + 3] = v.w;
  }
  __syncthreads();
#pragma unroll
  for (int p = 0; p < 4; p++) {
    const int slot = tid + p * 256;
    const int d = slot >> 4, c4 = slot & 15;
    __half b0 = __float2half_rn(t[c4 * 4 + 0][d]);
    __half b1 = __float2half_rn(t[c4 * 4 + 1][d]);
    __half b2 = __float2half_rn(t[c4 * 4 + 2][d]);
    __half b3 = __float2half_rn(t[c4 * 4 + 3][d]);
    uint32_t w0 = (uint32_t)__half_as_ushort(b0) |
                  ((uint32_t)__half_as_ushort(b1) << 16);
    uint32_t w1 = (uint32_t)__half_as_ushort(b2) |
                  ((uint32_t)__half_as_ushort(b3) << 16);
    const size_t off = ((size_t)bh * DK_ + d) * M_ + m0 + c4 * 4;
    uint2 ww = {w0, w1};
    *(uint2*)(g_vt + off) = ww;
  }
}

// ---------------- dense HMMA GEMM: out[16384,512] = A·Bt + bias -------------
template <bool WRITE_FLOAT, bool WRITE_SPLIT>
__global__ void __launch_bounds__(256) mma_gemm_kernel(
    const bf16* __restrict__ Ahi, const bf16* __restrict__ Alo,
    const bf16* __restrict__ Bhi, const bf16* __restrict__ Blo,
    const float* __restrict__ bias, float* __restrict__ out,
    bf16* __restrict__ ohi, bf16* __restrict__ olo, float oscale) {
  extern __shared__ __align__(128) char smem[];
  const uint32_t sbase = smem_u32(smem);
  const int tid = threadIdx.x, wid = tid >> 5, lane = tid & 31;
  const int bm = blockIdx.y * 128, bn = blockIdx.x * 128;
  constexpr uint32_t AH = 0, AL = 16384, BH = 32768, BL = 49152;
  const int mw = (wid & 1) * 64, nw = (wid >> 1) * 32;
  const int arow = (lane & 7) + (lane & 8);
  const uint32_t akb = (uint32_t)(lane & 16);
  const int brow = (lane & 7) + ((lane & 16) >> 1);
  const uint32_t bkb = (uint32_t)((lane & 8) * 2);
  float acc[4][4][4] = {};
  for (int kb = 0; kb < 8; kb++) {
    const int k0 = kb * 64;
    __syncthreads();
    load_tile<128>(smem, AH, Ahi + (size_t)bm * C_ + k0, C_, tid);
    load_tile<128>(smem, AL, Alo + (size_t)bm * C_ + k0, C_, tid);
    load_tile<128>(smem, BH, Bhi + (size_t)bn * C_ + k0, C_, tid);
    load_tile<128>(smem, BL, Blo + (size_t)bn * C_ + k0, C_, tid);
    __syncthreads();
#pragma unroll
    for (int ks = 0; ks < 4; ks++) {
      uint32_t ah[4][4], al[4][4], bh[4][2], bl[4][2];
#pragma unroll
      for (int mt = 0; mt < 4; mt++) {
        const uint32_t off = (uint32_t)((mw + mt * 16 + arow) * 128) + ks * 32 + akb;
        ldmat4(ah[mt], sbase + AH + swz(off));
        ldmat4(al[mt], sbase + AL + swz(off));
      }
#pragma unroll
      for (int np = 0; np < 2; np++) {
        const uint32_t off = (uint32_t)((nw + np * 16 + brow) * 128) + ks * 32 + bkb;
        uint32_t t4[4];
        ldmat4(t4, sbase + BH + swz(off));
        bh[np * 2][0] = t4[0]; bh[np * 2][1] = t4[1];
        bh[np * 2 + 1][0] = t4[2]; bh[np * 2 + 1][1] = t4[3];
        ldmat4(t4, sbase + BL + swz(off));
        bl[np * 2][0] = t4[0]; bl[np * 2][1] = t4[1];
        bl[np * 2 + 1][0] = t4[2]; bl[np * 2 + 1][1] = t4[3];
      }
#pragma unroll
      for (int mt = 0; mt < 4; mt++)
#pragma unroll
        for (int nt = 0; nt < 4; nt++) {
          mma16816(acc[mt][nt], ah[mt], bh[nt]);
          mma16816(acc[mt][nt], ah[mt], bl[nt]);
          mma16816(acc[mt][nt], al[mt], bh[nt]);
        }
    }
  }
  const int rbase = bm + mw + (lane >> 2);
  const int cbase = bn + nw + (lane & 3) * 2;
#pragma unroll
  for (int mt = 0; mt < 4; mt++)
#pragma unroll
    for (int nt = 0; nt < 4; nt++) {
      const int c = cbase + nt * 8;
      const float b0v = bias[c], b1v = bias[c + 1];
#pragma unroll
      for (int hr = 0; hr < 2; hr++) {
        const int r = rbase + mt * 16 + hr * 8;
        const float v0 = acc[mt][nt][hr * 2] + b0v;
        const float v1 = acc[mt][nt][hr * 2 + 1] + b1v;
        if (WRITE_FLOAT) {
          float2 o2 = {v0, v1};
          *(float2*)(out + (size_t)r * C_ + c) = o2;
        }
        if (WRITE_SPLIT) {
          uint32_t hw, lw;
          split2(v0 * oscale, v1 * oscale, hw, lw);
          *(uint32_t*)(ohi + (size_t)r * C_ + c) = hw;
          *(uint32_t*)(olo + (size_t)r * C_ + c) = lw;
        }
      }
    }
}

// ------- scores fused: e = exp((q/8)·k) -> fp16, row sums via atomics -------
__global__ void __launch_bounds__(256) scores_mma_kernel() {
  extern __shared__ __align__(128) char smem[];
  const uint32_t sbase = smem_u32(smem);
  const int tid = threadIdx.x, wid = tid >> 5, lane = tid & 31;
  const int bhz = blockIdx.z, b = bhz >> 3, h = bhz & 7;
  const int n0 = blockIdx.y << 7, m0 = blockIdx.x << 7;
  constexpr uint32_t AH = 0, AL = 16384, BH = 32768, BL = 49152;
  const int mw = (wid & 1) * 64, nw = (wid >> 1) * 32;
  const int arow = (lane & 7) + (lane & 8);
  const uint32_t akb = (uint32_t)(lane & 16);
  const int brow = (lane & 7) + ((lane & 16) >> 1);
  const uint32_t bkb = (uint32_t)((lane & 8) * 2);
  const size_t qoff = (size_t)(b * N_ + n0) * C_ + h * DK_;
  const size_t koff = (size_t)(b * M_ + m0) * C_ + h * DK_;
  load_tile<128>(smem, AH, g_qh + qoff, C_, tid);
  load_tile<128>(smem, AL, g_ql + qoff, C_, tid);
  load_tile<128>(smem, BH, g_kh + koff, C_, tid);
  load_tile<128>(smem, BL, g_kl + koff, C_, tid);
  __syncthreads();
  float acc[4][4][4] = {};
#pragma unroll
  for (int ks = 0; ks < 4; ks++) {
    uint32_t ah[4][4], al[4][4], bh[4][2], bl[4][2];
#pragma unroll
    for (int mt = 0; mt < 4; mt++) {
      const uint32_t off = (uint32_t)((mw + mt * 16 + arow) * 128) + ks * 32 + akb;
      ldmat4(ah[mt], sbase + AH + swz(off));
      ldmat4(al[mt], sbase + AL + swz(off));
    }
#pragma unroll
    for (int np = 0; np < 2; np++) {
      const uint32_t off = (uint32_t)((nw + np * 16 + brow) * 128) + ks * 32 + bkb;
      uint32_t t4[4];
      ldmat4(t4, sbase + BH + swz(off));
      bh[np * 2][0] = t4[0]; bh[np * 2][1] = t4[1];
      bh[np * 2 + 1][0] = t4[2]; bh[np * 2 + 1][1] = t4[3];
      ldmat4(t4, sbase + BL + swz(off));
      bl[np * 2][0] = t4[0]; bl[np * 2][1] = t4[1];
      bl[np * 2 + 1][0] = t4[2]; bl[np * 2 + 1][1] = t4[3];
    }
#pragma unroll
    for (int mt = 0; mt < 4; mt++)
#pragma unroll
      for (int nt = 0; nt < 4; nt++) {
        mma16816(acc[mt][nt], ah[mt], bh[nt]);
        mma16816(acc[mt][nt], ah[mt], bl[nt]);
        mma16816(acc[mt][nt], al[mt], bh[nt]);
      }
  }
  const int rbase = n0 + mw + (lane >> 2);
  const int cbase = m0 + nw + (lane & 3) * 2;
  __half* ep = g_e + (size_t)bhz * N_ * M_;
  float* rowsum = g_sum + (size_t)bhz * N_;
#pragma unroll
  for (int mt = 0; mt < 4; mt++) {
#pragma unroll
    for (int hr = 0; hr < 2; hr++) {
      const int r = rbase + mt * 16 + hr * 8;
      float ps = 0.f;
#pragma unroll
      for (int nt = 0; nt < 4; nt++) {
        const float e0 = __expf(acc[mt][nt][hr * 2]);
        const float e1 = __expf(acc[mt][nt][hr * 2 + 1]);
        ps += e0 + e1;
        __half eb0 = __float2half_rn(e0), eb1 = __float2half_rn(e1);
        uint32_t ew = (uint32_t)__half_as_ushort(eb0) |
                      ((uint32_t)__half_as_ushort(eb1) << 16);
        *(uint32_t*)(ep + (size_t)r * M_ + cbase + nt * 8) = ew;
      }
      ps += __shfl_xor_sync(0xffffffffu, ps, 1);
      ps += __shfl_xor_sync(0xffffffffu, ps, 2);
      if ((lane & 3) == 0) atomicAdd(rowsum + r, ps);
    }
  }
}

// ------ fused AV: cross-head renorm in SMEM + 8-head MMA + (q-o) split ------
// CTA = (b, 32-row n-block), all 8 heads. 512 threads, 2-stage cp.async.
__global__ void __launch_bounds__(512) av_fused_kernel() {
  extern __shared__ __align__(128) char smem[];
  const uint32_t sbase = smem_u32(smem);
  const int tid = threadIdx.x, wid = tid >> 5, lane = tid & 31;
  const int b = blockIdx.y;
  const int n0 = blockIdx.x * 32;
  float* rlS = (float*)smem;
  if (tid < 256) {
    const int h = tid >> 5, n = tid & 31;
    rlS[h * 32 + n] = 1.f / g_sum[(size_t)(b * H_ + h) * N_ + n0 + n];
  }
  const uint32_t stg0 = sbase + 1024;

  auto load_stage = [&](int st, int km) {
    const uint32_t sb = stg0 + (uint32_t)st * AVF_STAGE;
    const int m0 = km * 64;
#pragma unroll
    for (int p = 0; p < 4; p++) {   // e: 8 tiles of 32x64 fp16
      const int idx = tid + p * 512;
      const int h = idx >> 8, r = (idx >> 3) & 31, c = idx & 7;
      const uint32_t bo = (uint32_t)(r * 128 + c * 16);
      const void* src = g_e + ((size_t)(b * H_ + h) * N_ + n0 + r) * M_ + m0 + c * 8;
      asm volatile("cp.async.cg.shared.global [%0], [%1], 16;"
                   :: "r"(sb + h * 4096 + swz(bo)), "l"(src));
    }
#pragma unroll
    for (int p = 0; p < 8; p++) {   // V: 8 tiles of 64x64 fp16
      const int idx = tid + p * 512;
      const int h = idx >> 9, r = (idx >> 3) & 63, c = idx & 7;
      const uint32_t bo = (uint32_t)(r * 128 + c * 16);
      const void* src = g_vt + ((size_t)(b * H_ + h) * DK_ + r) * M_ + m0 + c * 8;
      asm volatile("cp.async.cg.shared.global [%0], [%1], 16;"
                   :: "r"(sb + 32768 + h * 8192 + swz(bo)), "l"(src));
    }
    asm volatile("cp.async.commit_group;" ::: "memory");
  };

  load_stage(0, 0);
  const int cn = tid >> 4, cmq = tid & 15;
  const uint32_t cvo = swz((uint32_t)(cn * 128 + cmq * 8));
  float rlv[8];
  const int rw = wid >> 3;       // row group (16 rows)
  const int hh = wid & 7;        // head
  const int arow = (lane & 7) + (lane & 8);
  const uint32_t akb = (uint32_t)(lane & 16);
  const int brow = (lane & 7) + ((lane & 16) >> 1);
  const uint32_t bkb = (uint32_t)((lane & 8) * 2);
  float acc[8][4] = {};
  for (int kb = 0; kb < 32; kb++) {
    __syncthreads();                       // prior MMA done; rlS visible at kb=0
    if (kb == 0) {
#pragma unroll
      for (int h = 0; h < 8; h++) rlv[h] = rlS[h * 32 + cn];
    }
    if (kb < 31) {
      load_stage((kb + 1) & 1, kb + 1);
      asm volatile("cp.async.wait_group 1;" ::: "memory");
    } else {
      asm volatile("cp.async.wait_group 0;" ::: "memory");
    }
    __syncthreads();
    const uint32_t cs = stg0 + (uint32_t)(kb & 1) * AVF_STAGE;
    char* csp = smem + 1024 + (size_t)(kb & 1) * AVF_STAGE;
    // ---- in-place e -> w conversion (cross-head renorm) ----
    {
      float p[8][4];
      float d0 = 1e-9f, d1 = 1e-9f, d2 = 1e-9f, d3 = 1e-9f;
#pragma unroll
      for (int h = 0; h < 8; h++) {
        uint2 e2 = *(uint2*)(csp + h * 4096 + cvo);
        p[h][0] = h2f(e2.x, 0) * rlv[h];
        p[h][1] = h2f(e2.x, 1) * rlv[h];
        p[h][2] = h2f(e2.y, 0) * rlv[h];
        p[h][3] = h2f(e2.y, 1) * rlv[h];
        d0 += p[h][0]; d1 += p[h][1]; d2 += p[h][2]; d3 += p[h][3];
      }
      const float i0 = 1.f / d0, i1 = 1.f / d1, i2 = 1.f / d2, i3 = 1.f / d3;
#pragma unroll
      for (int h = 0; h < 8; h++) {
        __half w0 = __float2half_rn(p[h][0] * i0);
        __half w1 = __float2half_rn(p[h][1] * i1);
        __half w2 = __float2half_rn(p[h][2] * i2);
        __half w3 = __float2half_rn(p[h][3] * i3);
        uint2 ww;
        ww.x = (uint32_t)__half_as_ushort(w0) | ((uint32_t)__half_as_ushort(w1) << 16);
        ww.y = (uint32_t)__half_as_ushort(w2) | ((uint32_t)__half_as_ushort(w3) << 16);
        *(uint2*)(csp + h * 4096 + cvo) = ww;
      }
    }
    __syncthreads();
    // ---- MMA: head hh, rows rw*16..+16, cols = all 64 d of head ----
    const uint32_t wbs = cs + hh * 4096;
    const uint32_t vbs = cs + 32768 + hh * 8192;
#pragma unroll
    for (int ks = 0; ks < 4; ks++) {
      uint32_t a4[4], bfr[8][2];
      {
        const uint32_t off = (uint32_t)((rw * 16 + arow) * 128) + ks * 32 + akb;
        ldmat4(a4, wbs + swz(off));
      }
#pragma unroll
      for (int np = 0; np < 4; np++) {
        const uint32_t off = (uint32_t)((np * 16 + brow) * 128) + ks * 32 + bkb;
        uint32_t t4[4];
        ldmat4(t4, vbs + swz(off));
        bfr[np * 2][0] = t4[0];     bfr[np * 2][1] = t4[1];
        bfr[np * 2 + 1][0] = t4[2]; bfr[np * 2 + 1][1] = t4[3];
      }
#pragma unroll
      for (int nt = 0; nt < 8; nt++) mma16816h(acc[nt], a4, bfr[nt]);
    }
  }
  // ---- epilogue: d = q - o, split to bf16 hi/lo ----
  const int gr = n0 + rw * 16 + (lane >> 2);
  const int gc0 = hh * DK_ + (lane & 3) * 2;
#pragma unroll
  for (int nt = 0; nt < 8; nt++) {
#pragma unroll
    for (int hr = 0; hr < 2; hr++) {
      const int r = gr + hr * 8;
      const int c = gc0 + nt * 8;
      const size_t off = (size_t)(b * N_ + r) * C_ + c;
      float2 q2 = *(const float2*)(g_q + off);
      const float v0 = q2.x - acc[nt][hr * 2];
      const float v1 = q2.y - acc[nt][hr * 2 + 1];
      uint32_t hw, lw;
      split2(v0, v1, hw, lw);
      *(uint32_t*)(g_dh + off) = hw;
      *(uint32_t*)(g_dl + off) = lw;
    }
  }
}

// --------------------- final: out = q + leaky_relu(LN(h)) -------------------
__global__ void __launch_bounds__(128) final_kernel(
    const float* __restrict__ gam, const float* __restrict__ bet,
    float* __restrict__ out) {
  const int row = blockIdx.x;
  const int t = threadIdx.x;
  float4 v = ((const float4*)(g_h + (size_t)row * C_))[t];
  float s  = v.x + v.y + v.z + v.w;
  float s2 = v.x * v.x + v.y * v.y + v.z * v.z + v.w * v.w;
#pragma unroll
  for (int o = 16; o > 0; o >>= 1) {
    s  += __shfl_xor_sync(0xffffffffu, s, o);
    s2 += __shfl_xor_sync(0xffffffffu, s2, o);
  }
  __shared__ float sa[4], sb[4];
  const int w = t >> 5;
  if ((t & 31) == 0) { sa[w] = s; sb[w] = s2; }
  __syncthreads();
  s  = sa[0] + sa[1] + sa[2] + sa[3];
  s2 = sb[0] + sb[1] + sb[2] + sb[3];
  const float mean = s * (1.f / C_);
  const float var  = s2 * (1.f / C_) - mean * mean;
  const float r = rsqrtf(var + 1e-5f);
  float4 gg = ((const float4*)gam)[t];
  float4 bb = ((const float4*)bet)[t];
  float4 q4 = ((const float4*)(g_q + (size_t)row * C_))[t];
  float4 o;
  float y;
  y = (v.x - mean) * r * gg.x + bb.x; y = y > 0.f ? y : 0.02f * y; o.x = q4.x + y;
  y = (v.y - mean) * r * gg.y + bb.y; y = y > 0.f ? y : 0.02f * y; o.y = q4.y + y;
  y = (v.z - mean) * r * gg.z + bb.z; y = y > 0.f ? y : 0.02f * y; o.z = q4.z + y;
  y = (v.w - mean) * r * gg.w + bb.w; y = y > 0.f ? y : 0.02f * y; o.w = q4.w + y;
  ((float4*)(out + (size_t)row * C_))[t] = o;
}

// ---------------------------------------------------------------------------
extern "C" void kernel_launch(void* const* d_in, const int* in_sizes, int n_in,
                              void* d_out, int out_size) {
  (void)in_sizes; (void)n_in; (void)out_size;
  const float* x   = (const float*)d_in[0];
  const float* y   = (const float*)d_in[1];
  const float* lxg = (const float*)d_in[2];
  const float* lxb = (const float*)d_in[3];
  const float* lyg = (const float*)d_in[4];
  const float* lyb = (const float*)d_in[5];
  const float* Wq  = (const float*)d_in[6];
  const float* bq  = (const float*)d_in[7];
  const float* Wk  = (const float*)d_in[8];
  const float* bk  = (const float*)d_in[9];
  const float* Wv  = (const float*)d_in[10];
  const float* bv  = (const float*)d_in[11];
  const float* Wc  = (const float*)d_in[12];
  const float* bc  = (const float*)d_in[13];
  const float* log_ = (const float*)d_in[14];
  const float* lob  = (const float*)d_in[15];
  float* out = (float*)d_out;

  static float *pq = nullptr, *pv, *ph;
  static bf16 *pxnh, *pxnl, *pynh, *pynl, *pqh, *pql, *pkh, *pkl;
  static bf16 *pwqh, *pwql, *pwkh, *pwkl, *pwvh, *pwvl, *pwch, *pwcl, *pdh, *pdl;
  if (!pq) {
    cudaGetSymbolAddress((void**)&pv,   g_v);
    cudaGetSymbolAddress((void**)&ph,   g_h);
    cudaGetSymbolAddress((void**)&pxnh, g_xnh);
    cudaGetSymbolAddress((void**)&pxnl, g_xnl);
    cudaGetSymbolAddress((void**)&pynh, g_ynh);
    cudaGetSymbolAddress((void**)&pynl, g_ynl);
    cudaGetSymbolAddress((void**)&pqh,  g_qh);
    cudaGetSymbolAddress((void**)&pql,  g_ql);
    cudaGetSymbolAddress((void**)&pkh,  g_kh);
    cudaGetSymbolAddress((void**)&pkl,  g_kl);
    cudaGetSymbolAddress((void**)&pwqh, g_wqh);
    cudaGetSymbolAddress((void**)&pwql, g_wql);
    cudaGetSymbolAddress((void**)&pwkh, g_wkh);
    cudaGetSymbolAddress((void**)&pwkl, g_wkl);
    cudaGetSymbolAddress((void**)&pwvh, g_wvh);
    cudaGetSymbolAddress((void**)&pwvl, g_wvl);
    cudaGetSymbolAddress((void**)&pwch, g_wch);
    cudaGetSymbolAddress((void**)&pwcl, g_wcl);
    cudaGetSymbolAddress((void**)&pdh,  g_dh);
    cudaGetSymbolAddress((void**)&pdl,  g_dl);
    cudaFuncSetAttribute(mma_gemm_kernel<true, true>,
                         cudaFuncAttributeMaxDynamicSharedMemorySize, SMEM_MMA);
    cudaFuncSetAttribute(mma_gemm_kernel<false, true>,
                         cudaFuncAttributeMaxDynamicSharedMemorySize, SMEM_MMA);
    cudaFuncSetAttribute(mma_gemm_kernel<true, false>,
                         cudaFuncAttributeMaxDynamicSharedMemorySize, SMEM_MMA);
    cudaFuncSetAttribute(scores_mma_kernel,
                         cudaFuncAttributeMaxDynamicSharedMemorySize, SMEM_MMA);
    cudaFuncSetAttribute(av_fused_kernel,
                         cudaFuncAttributeMaxDynamicSharedMemorySize, SMEM_AVF);
    cudaGetSymbolAddress((void**)&pq, g_q);  // last: guards re-entry
  }

  ln_split_kernel<<<RX, 128>>>(x, lxg, lxb, pxnh, pxnl);
  ln_split_kernel<<<RY, 128>>>(y, lyg, lyb, pynh, pynl);
  wtrans_kernel<<<dim3(8, 8), 256>>>(Wq, pwqh, pwql);
  wtrans_kernel<<<dim3(8, 8), 256>>>(Wk, pwkh, pwkl);
  wtrans_kernel<<<dim3(8, 8), 256>>>(Wv, pwvh, pwvl);
  split_kernel<<<C_ * C_ / 1024, 256>>>(Wc, pwch, pwcl);
  zero_sum_kernel<<<B_ * H_ * N_ / 256, 256>>>();

  dim3 gg(C_ / 128, RX / 128);
  mma_gemm_kernel<true, true><<<gg, 256, SMEM_MMA>>>(
      pxnh, pxnl, pwqh, pwql, bq, pq, pqh, pql, 0.125f);
  mma_gemm_kernel<false, true><<<gg, 256, SMEM_MMA>>>(
      pynh, pynl, pwkh, pwkl, bk, nullptr, pkh, pkl, 1.0f);
  mma_gemm_kernel<true, false><<<gg, 256, SMEM_MMA>>>(
      pynh, pynl, pwvh, pwvl, bv, pv, nullptr, nullptr, 0.f);
  vtrans_kernel<<<dim3(M_ / 64, B_ * H_), 256>>>();

  scores_mma_kernel<<<dim3(M_ / 128, N_ / 128, B_ * H_), 256, SMEM_MMA>>>();
  av_fused_kernel<<<dim3(N_ / 32, B_), 512, SMEM_AVF>>>();

  mma_gemm_kernel<true, false><<<gg, 256, SMEM_MMA>>>(
      pdh, pdl, pwch, pwcl, bc, ph, nullptr, nullptr, 0.f);
  final_kernel<<<RX, 128>>>(log_, lob, out);
}

// round 9
// speedup vs baseline: 3.4961x; 1.2100x over previous
#include <cuda_runtime.h>
#include <cuda_bf16.h>
#include <cuda_fp16.h>
#include <cstdint>
#include <math.h>

using bf16 = __nv_bfloat16;

namespace {
constexpr int B_  = 8;
constexpr int N_  = 2048;
constexpr int M_  = 2048;
constexpr int C_  = 512;
constexpr int H_  = 8;
constexpr int DK_ = 64;
constexpr int RX = B_ * N_;
constexpr int RY = B_ * M_;
constexpr int SMEM_MMA  = 65536;    // bf16 split GEMM: 4 tiles 128x64
constexpr int SMEM_HALF = 32768;    // fp16 GEMM/scores: 2 tiles 128x64
constexpr int AVF_STAGE = 98304;    // 8 e-tiles (32x64) + 8 V-tiles (64x64) fp16
constexpr int SMEM_AVF  = 1024 + 2 * AVF_STAGE;  // 197632
}

// ------------------------- scratch (device globals) -------------------------
__device__ float g_q [(size_t)RX * C_];
__device__ float g_h [(size_t)RX * C_];
__device__ float g_sum[B_ * H_ * N_];                    // softmax row sums
__device__ __half g_e [(size_t)B_ * H_ * N_ * M_];       // exp(scores) fp16
// bf16 hi/lo split operands (accuracy-critical path)
__device__ bf16 g_xnh[(size_t)RX * C_], g_xnl[(size_t)RX * C_];
__device__ bf16 g_dh [(size_t)RX * C_], g_dl [(size_t)RX * C_];   // q - o
__device__ bf16 g_wqh[C_ * C_], g_wql[C_ * C_];
__device__ bf16 g_wch[C_ * C_], g_wcl[C_ * C_];
// fp16 single operands (attention path)
__device__ __half g_ynf[(size_t)RY * C_];
__device__ __half g_qf [(size_t)RX * C_];   // q/8 fp16
__device__ __half g_kf [(size_t)RY * C_];
__device__ __half g_vf [(size_t)RY * C_];
__device__ __half g_vt [(size_t)B_ * H_ * DK_ * M_];     // V^T fp16
__device__ __half g_wkf[C_ * C_], g_wvf[C_ * C_];        // transposed fp16

// ------------------------------- helpers ------------------------------------
__device__ __forceinline__ uint32_t smem_u32(const void* p) {
  uint32_t a;
  asm("{ .reg .u64 t; cvta.to.shared.u64 t, %1; cvt.u32.u64 %0, t; }"
      : "=r"(a) : "l"(p));
  return a;
}
__device__ __forceinline__ uint32_t swz(uint32_t off) {
  return off ^ ((off >> 3) & 0x70);
}
__device__ __forceinline__ void ldmat4(uint32_t* r, uint32_t addr) {
  asm volatile("ldmatrix.sync.aligned.m8n8.x4.shared.b16 {%0,%1,%2,%3}, [%4];"
               : "=r"(r[0]), "=r"(r[1]), "=r"(r[2]), "=r"(r[3]) : "r"(addr));
}
__device__ __forceinline__ void mma16816(float* c, const uint32_t* a,
                                         const uint32_t* b) {
  asm volatile(
      "mma.sync.aligned.m16n8k16.row.col.f32.bf16.bf16.f32 "
      "{%0,%1,%2,%3}, {%4,%5,%6,%7}, {%8,%9}, {%0,%1,%2,%3};"
      : "+f"(c[0]), "+f"(c[1]), "+f"(c[2]), "+f"(c[3])
      : "r"(a[0]), "r"(a[1]), "r"(a[2]), "r"(a[3]), "r"(b[0]), "r"(b[1]));
}
__device__ __forceinline__ void mma16816h(float* c, const uint32_t* a,
                                          const uint32_t* b) {
  asm volatile(
      "mma.sync.aligned.m16n8k16.row.col.f32.f16.f16.f32 "
      "{%0,%1,%2,%3}, {%4,%5,%6,%7}, {%8,%9}, {%0,%1,%2,%3};"
      : "+f"(c[0]), "+f"(c[1]), "+f"(c[2]), "+f"(c[3])
      : "r"(a[0]), "r"(a[1]), "r"(a[2]), "r"(a[3]), "r"(b[0]), "r"(b[1]));
}
__device__ __forceinline__ void split2(float a, float b, uint32_t& hi, uint32_t& lo) {
  bf16 ha = __float2bfloat16(a), hb = __float2bfloat16(b);
  float ra = a - __bfloat162float(ha);
  float rb = b - __bfloat162float(hb);
  bf16 la = __float2bfloat16(ra), lb = __float2bfloat16(rb);
  hi = (uint32_t)__bfloat16_as_ushort(ha) | ((uint32_t)__bfloat16_as_ushort(hb) << 16);
  lo = (uint32_t)__bfloat16_as_ushort(la) | ((uint32_t)__bfloat16_as_ushort(lb) << 16);
}
__device__ __forceinline__ uint32_t packh2(float a, float b) {
  __half ha = __float2half_rn(a), hb = __float2half_rn(b);
  return (uint32_t)__half_as_ushort(ha) | ((uint32_t)__half_as_ushort(hb) << 16);
}
__device__ __forceinline__ float h2f(uint32_t w, int hi) {
  return __half2float(__ushort_as_half((unsigned short)(hi ? (w >> 16) : (w & 0xffff))));
}
// load NROWS x 64 elems (16-bit) tile (row-major, stride elems) -> SW128 SMEM
template <int NROWS, typename T>
__device__ __forceinline__ void load_tile(char* smem, uint32_t sbase,
                                          const T* __restrict__ g,
                                          size_t stride, int tid) {
#pragma unroll
  for (int p = 0; p < NROWS * 8 / 256; p++) {
    const int slot = tid + p * 256;
    const int r = slot >> 3, c = slot & 7;
    const uint32_t bo = (uint32_t)(r * 128 + c * 16);
    uint4 v = *(const uint4*)(g + (size_t)r * stride + c * 8);
    *(uint4*)(smem + sbase + swz(bo)) = v;
  }
}

// ---------------------- LayerNorm -> bf16 hi/lo (x) -------------------------
__global__ void __launch_bounds__(128) ln_split_kernel(
    const float* __restrict__ x, const float* __restrict__ gam,
    const float* __restrict__ bet, bf16* __restrict__ oh, bf16* __restrict__ ol) {
  const int row = blockIdx.x;
  const int t = threadIdx.x;
  float4 v = ((const float4*)(x + (size_t)row * C_))[t];
  float s  = v.x + v.y + v.z + v.w;
  float s2 = v.x * v.x + v.y * v.y + v.z * v.z + v.w * v.w;
#pragma unroll
  for (int o = 16; o > 0; o >>= 1) {
    s  += __shfl_xor_sync(0xffffffffu, s, o);
    s2 += __shfl_xor_sync(0xffffffffu, s2, o);
  }
  __shared__ float sa[4], sb[4];
  const int w = t >> 5;
  if ((t & 31) == 0) { sa[w] = s; sb[w] = s2; }
  __syncthreads();
  s  = sa[0] + sa[1] + sa[2] + sa[3];
  s2 = sb[0] + sb[1] + sb[2] + sb[3];
  const float mean = s * (1.f / C_);
  const float var  = s2 * (1.f / C_) - mean * mean;
  const float r = rsqrtf(var + 1e-5f);
  float4 gg = ((const float4*)gam)[t];
  float4 bb = ((const float4*)bet)[t];
  float ox = (v.x - mean) * r * gg.x + bb.x;
  float oy = (v.y - mean) * r * gg.y + bb.y;
  float oz = (v.z - mean) * r * gg.z + bb.z;
  float ow = (v.w - mean) * r * gg.w + bb.w;
  uint32_t h0, l0, h1, l1;
  split2(ox, oy, h0, l0);
  split2(oz, ow, h1, l1);
  const size_t off = (size_t)row * C_ + t * 4;
  uint2 hh = {h0, h1}, ll = {l0, l1};
  *(uint2*)(oh + off) = hh;
  *(uint2*)(ol + off) = ll;
}

// ---------------------- LayerNorm -> fp16 single (y) ------------------------
__global__ void __launch_bounds__(128) ln_half_kernel(
    const float* __restrict__ x, const float* __restrict__ gam,
    const float* __restrict__ bet, __half* __restrict__ oh) {
  const int row = blockIdx.x;
  const int t = threadIdx.x;
  float4 v = ((const float4*)(x + (size_t)row * C_))[t];
  float s  = v.x + v.y + v.z + v.w;
  float s2 = v.x * v.x + v.y * v.y + v.z * v.z + v.w * v.w;
#pragma unroll
  for (int o = 16; o > 0; o >>= 1) {
    s  += __shfl_xor_sync(0xffffffffu, s, o);
    s2 += __shfl_xor_sync(0xffffffffu, s2, o);
  }
  __shared__ float sa[4], sb[4];
  const int w = t >> 5;
  if ((t & 31) == 0) { sa[w] = s; sb[w] = s2; }
  __syncthreads();
  s  = sa[0] + sa[1] + sa[2] + sa[3];
  s2 = sb[0] + sb[1] + sb[2] + sb[3];
  const float mean = s * (1.f / C_);
  const float var  = s2 * (1.f / C_) - mean * mean;
  const float r = rsqrtf(var + 1e-5f);
  float4 gg = ((const float4*)gam)[t];
  float4 bb = ((const float4*)bet)[t];
  uint2 hh;
  hh.x = packh2((v.x - mean) * r * gg.x + bb.x, (v.y - mean) * r * gg.y + bb.y);
  hh.y = packh2((v.z - mean) * r * gg.z + bb.z, (v.w - mean) * r * gg.w + bb.w);
  *(uint2*)(oh + (size_t)row * C_ + t * 4) = hh;
}

// ------------------- weight transpose + split bf16 (Wq) ---------------------
__global__ void __launch_bounds__(256) wtrans_kernel(
    const float* __restrict__ W, bf16* __restrict__ th, bf16* __restrict__ tl) {
  __shared__ float t[64][65];
  const int c0 = blockIdx.y * 64, j0 = blockIdx.x * 64;
  const int tid = threadIdx.x;
#pragma unroll
  for (int p = 0; p < 4; p++) {
    const int slot = tid + p * 256;
    const int r = slot >> 4, c4 = slot & 15;
    float4 v = *(const float4*)(W + (size_t)(c0 + r) * C_ + j0 + c4 * 4);
    t[r][c4 * 4 + 0] = v.x; t[r][c4 * 4 + 1] = v.y;
    t[r][c4 * 4 + 2] = v.z; t[r][c4 * 4 + 3] = v.w;
  }
  __syncthreads();
#pragma unroll
  for (int p = 0; p < 4; p++) {
    const int slot = tid + p * 256;
    const int jr = slot >> 4, c4 = slot & 15;
    float v0 = t[c4 * 4 + 0][jr], v1 = t[c4 * 4 + 1][jr];
    float v2 = t[c4 * 4 + 2][jr], v3 = t[c4 * 4 + 3][jr];
    uint32_t h0, l0, h1, l1;
    split2(v0, v1, h0, l0);
    split2(v2, v3, h1, l1);
    const size_t off = (size_t)(j0 + jr) * C_ + c0 + c4 * 4;
    uint2 hh = {h0, h1}, ll = {l0, l1};
    *(uint2*)(th + off) = hh;
    *(uint2*)(tl + off) = ll;
  }
}

// ------------------- weight transpose fp16 (Wk/Wv) --------------------------
__global__ void __launch_bounds__(256) wtrans_half_kernel(
    const float* __restrict__ W, __half* __restrict__ th) {
  __shared__ float t[64][65];
  const int c0 = blockIdx.y * 64, j0 = blockIdx.x * 64;
  const int tid = threadIdx.x;
#pragma unroll
  for (int p = 0; p < 4; p++) {
    const int slot = tid + p * 256;
    const int r = slot >> 4, c4 = slot & 15;
    float4 v = *(const float4*)(W + (size_t)(c0 + r) * C_ + j0 + c4 * 4);
    t[r][c4 * 4 + 0] = v.x; t[r][c4 * 4 + 1] = v.y;
    t[r][c4 * 4 + 2] = v.z; t[r][c4 * 4 + 3] = v.w;
  }
  __syncthreads();
#pragma unroll
  for (int p = 0; p < 4; p++) {
    const int slot = tid + p * 256;
    const int jr = slot >> 4, c4 = slot & 15;
    uint2 hh;
    hh.x = packh2(t[c4 * 4 + 0][jr], t[c4 * 4 + 1][jr]);
    hh.y = packh2(t[c4 * 4 + 2][jr], t[c4 * 4 + 3][jr]);
    *(uint2*)(th + (size_t)(j0 + jr) * C_ + c0 + c4 * 4) = hh;
  }
}

// ------------------------- elementwise split (Wc) ---------------------------
__global__ void __launch_bounds__(256) split_kernel(
    const float* __restrict__ a, bf16* __restrict__ oh, bf16* __restrict__ ol) {
  const size_t i4 = (size_t)blockIdx.x * 256 + threadIdx.x;
  float4 v = ((const float4*)a)[i4];
  uint32_t h0, l0, h1, l1;
  split2(v.x, v.y, h0, l0);
  split2(v.z, v.w, h1, l1);
  uint2 hh = {h0, h1}, ll = {l0, l1};
  *(uint2*)(oh + i4 * 4) = hh;
  *(uint2*)(ol + i4 * 4) = ll;
}

// ---------------------- zero softmax row-sum accumulator --------------------
__global__ void __launch_bounds__(256) zero_sum_kernel() {
  g_sum[blockIdx.x * 256 + threadIdx.x] = 0.f;
}

// --------------------- V transpose to [bh][d][m] fp16 -----------------------
__global__ void __launch_bounds__(256) vtrans_kernel() {
  __shared__ float t[64][65];
  const int bh = blockIdx.y;
  const int b = bh >> 3, h = bh & 7;
  const int m0 = blockIdx.x * 64;
  const int tid = threadIdx.x;
#pragma unroll
  for (int p = 0; p < 4; p++) {
    const int slot = tid + p * 256;
    const int r = slot >> 4, c4 = slot & 15;
    uint2 v2 = *(const uint2*)(g_vf + (size_t)(b * M_ + m0 + r) * C_ + h * DK_ + c4 * 4);
    t[r][c4 * 4 + 0] = h2f(v2.x, 0); t[r][c4 * 4 + 1] = h2f(v2.x, 1);
    t[r][c4 * 4 + 2] = h2f(v2.y, 0); t[r][c4 * 4 + 3] = h2f(v2.y, 1);
  }
  __syncthreads();
#pragma unroll
  for (int p = 0; p < 4; p++) {
    const int slot = tid + p * 256;
    const int d = slot >> 4, c4 = slot & 15;
    uint2 ww;
    ww.x = packh2(t[c4 * 4 + 0][d], t[c4 * 4 + 1][d]);
    ww.y = packh2(t[c4 * 4 + 2][d], t[c4 * 4 + 3][d]);
    *(uint2*)(g_vt + ((size_t)bh * DK_ + d) * M_ + m0 + c4 * 4) = ww;
  }
}

// -------- dense bf16 3-MMA GEMM (Q and Wc paths): out = A·Bt + bias ---------
template <bool WRITE_HALF>
__global__ void __launch_bounds__(256) mma_gemm_kernel(
    const bf16* __restrict__ Ahi, const bf16* __restrict__ Alo,
    const bf16* __restrict__ Bhi, const bf16* __restrict__ Blo,
    const float* __restrict__ bias, float* __restrict__ out,
    __half* __restrict__ outh, float hscale) {
  extern __shared__ __align__(128) char smem[];
  const uint32_t sbase = smem_u32(smem);
  const int tid = threadIdx.x, wid = tid >> 5, lane = tid & 31;
  const int bm = blockIdx.y * 128, bn = blockIdx.x * 128;
  constexpr uint32_t AH = 0, AL = 16384, BH = 32768, BL = 49152;
  const int mw = (wid & 1) * 64, nw = (wid >> 1) * 32;
  const int arow = (lane & 7) + (lane & 8);
  const uint32_t akb = (uint32_t)(lane & 16);
  const int brow = (lane & 7) + ((lane & 16) >> 1);
  const uint32_t bkb = (uint32_t)((lane & 8) * 2);
  float acc[4][4][4] = {};
  for (int kb = 0; kb < 8; kb++) {
    const int k0 = kb * 64;
    __syncthreads();
    load_tile<128>(smem, AH, Ahi + (size_t)bm * C_ + k0, C_, tid);
    load_tile<128>(smem, AL, Alo + (size_t)bm * C_ + k0, C_, tid);
    load_tile<128>(smem, BH, Bhi + (size_t)bn * C_ + k0, C_, tid);
    load_tile<128>(smem, BL, Blo + (size_t)bn * C_ + k0, C_, tid);
    __syncthreads();
#pragma unroll
    for (int ks = 0; ks < 4; ks++) {
      uint32_t ah[4][4], al[4][4], bh[4][2], bl[4][2];
#pragma unroll
      for (int mt = 0; mt < 4; mt++) {
        const uint32_t off = (uint32_t)((mw + mt * 16 + arow) * 128) + ks * 32 + akb;
        ldmat4(ah[mt], sbase + AH + swz(off));
        ldmat4(al[mt], sbase + AL + swz(off));
      }
#pragma unroll
      for (int np = 0; np < 2; np++) {
        const uint32_t off = (uint32_t)((nw + np * 16 + brow) * 128) + ks * 32 + bkb;
        uint32_t t4[4];
        ldmat4(t4, sbase + BH + swz(off));
        bh[np * 2][0] = t4[0]; bh[np * 2][1] = t4[1];
        bh[np * 2 + 1][0] = t4[2]; bh[np * 2 + 1][1] = t4[3];
        ldmat4(t4, sbase + BL + swz(off));
        bl[np * 2][0] = t4[0]; bl[np * 2][1] = t4[1];
        bl[np * 2 + 1][0] = t4[2]; bl[np * 2 + 1][1] = t4[3];
      }
#pragma unroll
      for (int mt = 0; mt < 4; mt++)
#pragma unroll
        for (int nt = 0; nt < 4; nt++) {
          mma16816(acc[mt][nt], ah[mt], bh[nt]);
          mma16816(acc[mt][nt], ah[mt], bl[nt]);
          mma16816(acc[mt][nt], al[mt], bh[nt]);
        }
    }
  }
  const int rbase = bm + mw + (lane >> 2);
  const int cbase = bn + nw + (lane & 3) * 2;
#pragma unroll
  for (int mt = 0; mt < 4; mt++)
#pragma unroll
    for (int nt = 0; nt < 4; nt++) {
      const int c = cbase + nt * 8;
      const float b0v = bias[c], b1v = bias[c + 1];
#pragma unroll
      for (int hr = 0; hr < 2; hr++) {
        const int r = rbase + mt * 16 + hr * 8;
        const float v0 = acc[mt][nt][hr * 2] + b0v;
        const float v1 = acc[mt][nt][hr * 2 + 1] + b1v;
        float2 o2 = {v0, v1};
        *(float2*)(out + (size_t)r * C_ + c) = o2;
        if (WRITE_HALF)
          *(uint32_t*)(outh + (size_t)r * C_ + c) = packh2(v0 * hscale, v1 * hscale);
      }
    }
}

// --------- dense fp16 1-MMA GEMM (K and V paths): outh = A·Bt + bias --------
__global__ void __launch_bounds__(256) mma_gemm_half_kernel(
    const __half* __restrict__ A, const __half* __restrict__ Bm,
    const float* __restrict__ bias, __half* __restrict__ outh) {
  extern __shared__ __align__(128) char smem[];
  const uint32_t sbase = smem_u32(smem);
  const int tid = threadIdx.x, wid = tid >> 5, lane = tid & 31;
  const int bm = blockIdx.y * 128, bn = blockIdx.x * 128;
  constexpr uint32_t AH = 0, BH = 16384;
  const int mw = (wid & 1) * 64, nw = (wid >> 1) * 32;
  const int arow = (lane & 7) + (lane & 8);
  const uint32_t akb = (uint32_t)(lane & 16);
  const int brow = (lane & 7) + ((lane & 16) >> 1);
  const uint32_t bkb = (uint32_t)((lane & 8) * 2);
  float acc[4][4][4] = {};
  for (int kb = 0; kb < 8; kb++) {
    const int k0 = kb * 64;
    __syncthreads();
    load_tile<128>(smem, AH, A + (size_t)bm * C_ + k0, C_, tid);
    load_tile<128>(smem, BH, Bm + (size_t)bn * C_ + k0, C_, tid);
    __syncthreads();
#pragma unroll
    for (int ks = 0; ks < 4; ks++) {
      uint32_t ah[4][4], bh[4][2];
#pragma unroll
      for (int mt = 0; mt < 4; mt++) {
        const uint32_t off = (uint32_t)((mw + mt * 16 + arow) * 128) + ks * 32 + akb;
        ldmat4(ah[mt], sbase + AH + swz(off));
      }
#pragma unroll
      for (int np = 0; np < 2; np++) {
        const uint32_t off = (uint32_t)((nw + np * 16 + brow) * 128) + ks * 32 + bkb;
        uint32_t t4[4];
        ldmat4(t4, sbase + BH + swz(off));
        bh[np * 2][0] = t4[0]; bh[np * 2][1] = t4[1];
        bh[np * 2 + 1][0] = t4[2]; bh[np * 2 + 1][1] = t4[3];
      }
#pragma unroll
      for (int mt = 0; mt < 4; mt++)
#pragma unroll
        for (int nt = 0; nt < 4; nt++)
          mma16816h(acc[mt][nt], ah[mt], bh[nt]);
    }
  }
  const int rbase = bm + mw + (lane >> 2);
  const int cbase = bn + nw + (lane & 3) * 2;
#pragma unroll
  for (int mt = 0; mt < 4; mt++)
#pragma unroll
    for (int nt = 0; nt < 4; nt++) {
      const int c = cbase + nt * 8;
      const float b0v = bias[c], b1v = bias[c + 1];
#pragma unroll
      for (int hr = 0; hr < 2; hr++) {
        const int r = rbase + mt * 16 + hr * 8;
        *(uint32_t*)(outh + (size_t)r * C_ + c) =
            packh2(acc[mt][nt][hr * 2] + b0v, acc[mt][nt][hr * 2 + 1] + b1v);
      }
    }
}

// ----- scores (fp16 1-MMA): e = exp((q/8)·k) -> fp16, row sums via atomics --
__global__ void __launch_bounds__(256) scores_mma_kernel() {
  extern __shared__ __align__(128) char smem[];
  const uint32_t sbase = smem_u32(smem);
  const int tid = threadIdx.x, wid = tid >> 5, lane = tid & 31;
  const int bhz = blockIdx.z, b = bhz >> 3, h = bhz & 7;
  const int n0 = blockIdx.y << 7, m0 = blockIdx.x << 7;
  constexpr uint32_t AH = 0, BH = 16384;
  const int mw = (wid & 1) * 64, nw = (wid >> 1) * 32;
  const int arow = (lane & 7) + (lane & 8);
  const uint32_t akb = (uint32_t)(lane & 16);
  const int brow = (lane & 7) + ((lane & 16) >> 1);
  const uint32_t bkb = (uint32_t)((lane & 8) * 2);
  load_tile<128>(smem, AH, g_qf + (size_t)(b * N_ + n0) * C_ + h * DK_, C_, tid);
  load_tile<128>(smem, BH, g_kf + (size_t)(b * M_ + m0) * C_ + h * DK_, C_, tid);
  __syncthreads();
  float acc[4][4][4] = {};
#pragma unroll
  for (int ks = 0; ks < 4; ks++) {
    uint32_t ah[4][4], bh[4][2];
#pragma unroll
    for (int mt = 0; mt < 4; mt++) {
      const uint32_t off = (uint32_t)((mw + mt * 16 + arow) * 128) + ks * 32 + akb;
      ldmat4(ah[mt], sbase + AH + swz(off));
    }
#pragma unroll
    for (int np = 0; np < 2; np++) {
      const uint32_t off = (uint32_t)((nw + np * 16 + brow) * 128) + ks * 32 + bkb;
      uint32_t t4[4];
      ldmat4(t4, sbase + BH + swz(off));
      bh[np * 2][0] = t4[0]; bh[np * 2][1] = t4[1];
      bh[np * 2 + 1][0] = t4[2]; bh[np * 2 + 1][1] = t4[3];
    }
#pragma unroll
    for (int mt = 0; mt < 4; mt++)
#pragma unroll
      for (int nt = 0; nt < 4; nt++)
        mma16816h(acc[mt][nt], ah[mt], bh[nt]);
  }
  const int rbase = n0 + mw + (lane >> 2);
  const int cbase = m0 + nw + (lane & 3) * 2;
  __half* ep = g_e + (size_t)bhz * N_ * M_;
  float* rowsum = g_sum + (size_t)bhz * N_;
#pragma unroll
  for (int mt = 0; mt < 4; mt++) {
#pragma unroll
    for (int hr = 0; hr < 2; hr++) {
      const int r = rbase + mt * 16 + hr * 8;
      float ps = 0.f;
#pragma unroll
      for (int nt = 0; nt < 4; nt++) {
        const float e0 = __expf(acc[mt][nt][hr * 2]);
        const float e1 = __expf(acc[mt][nt][hr * 2 + 1]);
        ps += e0 + e1;
        *(uint32_t*)(ep + (size_t)r * M_ + cbase + nt * 8) = packh2(e0, e1);
      }
      ps += __shfl_xor_sync(0xffffffffu, ps, 1);
      ps += __shfl_xor_sync(0xffffffffu, ps, 2);
      if ((lane & 3) == 0) atomicAdd(rowsum + r, ps);
    }
  }
}

// ------ fused AV: cross-head renorm in SMEM + 8-head MMA + (q-o) split ------
__global__ void __launch_bounds__(512) av_fused_kernel() {
  extern __shared__ __align__(128) char smem[];
  const uint32_t sbase = smem_u32(smem);
  const int tid = threadIdx.x, wid = tid >> 5, lane = tid & 31;
  const int b = blockIdx.y;
  const int n0 = blockIdx.x * 32;
  float* rlS = (float*)smem;
  if (tid < 256) {
    const int h = tid >> 5, n = tid & 31;
    rlS[h * 32 + n] = 1.f / g_sum[(size_t)(b * H_ + h) * N_ + n0 + n];
  }
  const uint32_t stg0 = sbase + 1024;

  auto load_stage = [&](int st, int km) {
    const uint32_t sb = stg0 + (uint32_t)st * AVF_STAGE;
    const int m0 = km * 64;
#pragma unroll
    for (int p = 0; p < 4; p++) {   // e: 8 tiles of 32x64 fp16
      const int idx = tid + p * 512;
      const int h = idx >> 8, r = (idx >> 3) & 31, c = idx & 7;
      const uint32_t bo = (uint32_t)(r * 128 + c * 16);
      const void* src = g_e + ((size_t)(b * H_ + h) * N_ + n0 + r) * M_ + m0 + c * 8;
      asm volatile("cp.async.cg.shared.global [%0], [%1], 16;"
                   :: "r"(sb + h * 4096 + swz(bo)), "l"(src));
    }
#pragma unroll
    for (int p = 0; p < 8; p++) {   // V: 8 tiles of 64x64 fp16
      const int idx = tid + p * 512;
      const int h = idx >> 9, r = (idx >> 3) & 63, c = idx & 7;
      const uint32_t bo = (uint32_t)(r * 128 + c * 16);
      const void* src = g_vt + ((size_t)(b * H_ + h) * DK_ + r) * M_ + m0 + c * 8;
      asm volatile("cp.async.cg.shared.global [%0], [%1], 16;"
                   :: "r"(sb + 32768 + h * 8192 + swz(bo)), "l"(src));
    }
    asm volatile("cp.async.commit_group;" ::: "memory");
  };

  load_stage(0, 0);
  const int cn = tid >> 4, cmq = tid & 15;
  const uint32_t cvo = swz((uint32_t)(cn * 128 + cmq * 8));
  float rlv[8];
  const int rw = wid >> 3;       // row group (16 rows)
  const int hh = wid & 7;        // head
  const int arow = (lane & 7) + (lane & 8);
  const uint32_t akb = (uint32_t)(lane & 16);
  const int brow = (lane & 7) + ((lane & 16) >> 1);
  const uint32_t bkb = (uint32_t)((lane & 8) * 2);
  float acc[8][4] = {};
  for (int kb = 0; kb < 32; kb++) {
    __syncthreads();
    if (kb == 0) {
#pragma unroll
      for (int h = 0; h < 8; h++) rlv[h] = rlS[h * 32 + cn];
    }
    if (kb < 31) {
      load_stage((kb + 1) & 1, kb + 1);
      asm volatile("cp.async.wait_group 1;" ::: "memory");
    } else {
      asm volatile("cp.async.wait_group 0;" ::: "memory");
    }
    __syncthreads();
    const uint32_t cs = stg0 + (uint32_t)(kb & 1) * AVF_STAGE;
    char* csp = smem + 1024 + (size_t)(kb & 1) * AVF_STAGE;
    {
      float p[8][4];
      float d0 = 1e-9f, d1 = 1e-9f, d2 = 1e-9f, d3 = 1e-9f;
#pragma unroll
      for (int h = 0; h < 8; h++) {
        uint2 e2 = *(uint2*)(csp + h * 4096 + cvo);
        p[h][0] = h2f(e2.x, 0) * rlv[h];
        p[h][1] = h2f(e2.x, 1) * rlv[h];
        p[h][2] = h2f(e2.y, 0) * rlv[h];
        p[h][3] = h2f(e2.y, 1) * rlv[h];
        d0 += p[h][0]; d1 += p[h][1]; d2 += p[h][2]; d3 += p[h][3];
      }
      const float i0 = 1.f / d0, i1 = 1.f / d1, i2 = 1.f / d2, i3 = 1.f / d3;
#pragma unroll
      for (int h = 0; h < 8; h++) {
        uint2 ww;
        ww.x = packh2(p[h][0] * i0, p[h][1] * i1);
        ww.y = packh2(p[h][2] * i2, p[h][3] * i3);
        *(uint2*)(csp + h * 4096 + cvo) = ww;
      }
    }
    __syncthreads();
    const uint32_t wbs = cs + hh * 4096;
    const uint32_t vbs = cs + 32768 + hh * 8192;
#pragma unroll
    for (int ks = 0; ks < 4; ks++) {
      uint32_t a4[4], bfr[8][2];
      {
        const uint32_t off = (uint32_t)((rw * 16 + arow) * 128) + ks * 32 + akb;
        ldmat4(a4, wbs + swz(off));
      }
#pragma unroll
      for (int np = 0; np < 4; np++) {
        const uint32_t off = (uint32_t)((np * 16 + brow) * 128) + ks * 32 + bkb;
        uint32_t t4[4];
        ldmat4(t4, vbs + swz(off));
        bfr[np * 2][0] = t4[0];     bfr[np * 2][1] = t4[1];
        bfr[np * 2 + 1][0] = t4[2]; bfr[np * 2 + 1][1] = t4[3];
      }
#pragma unroll
      for (int nt = 0; nt < 8; nt++) mma16816h(acc[nt], a4, bfr[nt]);
    }
  }
  const int gr = n0 + rw * 16 + (lane >> 2);
  const int gc0 = hh * DK_ + (lane & 3) * 2;
#pragma unroll
  for (int nt = 0; nt < 8; nt++) {
#pragma unroll
    for (int hr = 0; hr < 2; hr++) {
      const int r = gr + hr * 8;
      const int c = gc0 + nt * 8;
      const size_t off = (size_t)(b * N_ + r) * C_ + c;
      float2 q2 = *(const float2*)(g_q + off);
      const float v0 = q2.x - acc[nt][hr * 2];
      const float v1 = q2.y - acc[nt][hr * 2 + 1];
      uint32_t hw, lw;
      split2(v0, v1, hw, lw);
      *(uint32_t*)(g_dh + off) = hw;
      *(uint32_t*)(g_dl + off) = lw;
    }
  }
}

// --------------------- final: out = q + leaky_relu(LN(h)) -------------------
__global__ void __launch_bounds__(128) final_kernel(
    const float* __restrict__ gam, const float* __restrict__ bet,
    float* __restrict__ out) {
  const int row = blockIdx.x;
  const int t = threadIdx.x;
  float4 v = ((const float4*)(g_h + (size_t)row * C_))[t];
  float s  = v.x + v.y + v.z + v.w;
  float s2 = v.x * v.x + v.y * v.y + v.z * v.z + v.w * v.w;
#pragma unroll
  for (int o = 16; o > 0; o >>= 1) {
    s  += __shfl_xor_sync(0xffffffffu, s, o);
    s2 += __shfl_xor_sync(0xffffffffu, s2, o);
  }
  __shared__ float sa[4], sb[4];
  const int w = t >> 5;
  if ((t & 31) == 0) { sa[w] = s; sb[w] = s2; }
  __syncthreads();
  s  = sa[0] + sa[1] + sa[2] + sa[3];
  s2 = sb[0] + sb[1] + sb[2] + sb[3];
  const float mean = s * (1.f / C_);
  const float var  = s2 * (1.f / C_) - mean * mean;
  const float r = rsqrtf(var + 1e-5f);
  float4 gg = ((const float4*)gam)[t];
  float4 bb = ((const float4*)bet)[t];
  float4 q4 = ((const float4*)(g_q + (size_t)row * C_))[t];
  float4 o;
  float y;
  y = (v.x - mean) * r * gg.x + bb.x; y = y > 0.f ? y : 0.02f * y; o.x = q4.x + y;
  y = (v.y - mean) * r * gg.y + bb.y; y = y > 0.f ? y : 0.02f * y; o.y = q4.y + y;
  y = (v.z - mean) * r * gg.z + bb.z; y = y > 0.f ? y : 0.02f * y; o.z = q4.z + y;
  y = (v.w - mean) * r * gg.w + bb.w; y = y > 0.f ? y : 0.02f * y; o.w = q4.w + y;
  ((float4*)(out + (size_t)row * C_))[t] = o;
}

// ---------------------------------------------------------------------------
extern "C" void kernel_launch(void* const* d_in, const int* in_sizes, int n_in,
                              void* d_out, int out_size) {
  (void)in_sizes; (void)n_in; (void)out_size;
  const float* x   = (const float*)d_in[0];
  const float* y   = (const float*)d_in[1];
  const float* lxg = (const float*)d_in[2];
  const float* lxb = (const float*)d_in[3];
  const float* lyg = (const float*)d_in[4];
  const float* lyb = (const float*)d_in[5];
  const float* Wq  = (const float*)d_in[6];
  const float* bq  = (const float*)d_in[7];
  const float* Wk  = (const float*)d_in[8];
  const float* bk  = (const float*)d_in[9];
  const float* Wv  = (const float*)d_in[10];
  const float* bv  = (const float*)d_in[11];
  const float* Wc  = (const float*)d_in[12];
  const float* bc  = (const float*)d_in[13];
  const float* log_ = (const float*)d_in[14];
  const float* lob  = (const float*)d_in[15];
  float* out = (float*)d_out;

  static float *pq = nullptr, *ph;
  static bf16 *pxnh, *pxnl, *pwqh, *pwql, *pwch, *pwcl, *pdh, *pdl;
  static __half *pynf, *pqf, *pkf, *pvf, *pwkf, *pwvf;
  if (!pq) {
    cudaGetSymbolAddress((void**)&ph,   g_h);
    cudaGetSymbolAddress((void**)&pxnh, g_xnh);
    cudaGetSymbolAddress((void**)&pxnl, g_xnl);
    cudaGetSymbolAddress((void**)&pwqh, g_wqh);
    cudaGetSymbolAddress((void**)&pwql, g_wql);
    cudaGetSymbolAddress((void**)&pwch, g_wch);
    cudaGetSymbolAddress((void**)&pwcl, g_wcl);
    cudaGetSymbolAddress((void**)&pdh,  g_dh);
    cudaGetSymbolAddress((void**)&pdl,  g_dl);
    cudaGetSymbolAddress((void**)&pynf, g_ynf);
    cudaGetSymbolAddress((void**)&pqf,  g_qf);
    cudaGetSymbolAddress((void**)&pkf,  g_kf);
    cudaGetSymbolAddress((void**)&pvf,  g_vf);
    cudaGetSymbolAddress((void**)&pwkf, g_wkf);
    cudaGetSymbolAddress((void**)&pwvf, g_wvf);
    cudaFuncSetAttribute(mma_gemm_kernel<true>,
                         cudaFuncAttributeMaxDynamicSharedMemorySize, SMEM_MMA);
    cudaFuncSetAttribute(mma_gemm_kernel<false>,
                         cudaFuncAttributeMaxDynamicSharedMemorySize, SMEM_MMA);
    cudaFuncSetAttribute(mma_gemm_half_kernel,
                         cudaFuncAttributeMaxDynamicSharedMemorySize, SMEM_HALF);
    cudaFuncSetAttribute(scores_mma_kernel,
                         cudaFuncAttributeMaxDynamicSharedMemorySize, SMEM_HALF);
    cudaFuncSetAttribute(av_fused_kernel,
                         cudaFuncAttributeMaxDynamicSharedMemorySize, SMEM_AVF);
    cudaGetSymbolAddress((void**)&pq, g_q);  // last: guards re-entry
  }

  ln_split_kernel<<<RX, 128>>>(x, lxg, lxb, pxnh, pxnl);
  ln_half_kernel<<<RY, 128>>>(y, lyg, lyb, pynf);
  wtrans_kernel<<<dim3(8, 8), 256>>>(Wq, pwqh, pwql);
  wtrans_half_kernel<<<dim3(8, 8), 256>>>(Wk, pwkf);
  wtrans_half_kernel<<<dim3(8, 8), 256>>>(Wv, pwvf);
  split_kernel<<<C_ * C_ / 1024, 256>>>(Wc, pwch, pwcl);
  zero_sum_kernel<<<B_ * H_ * N_ / 256, 256>>>();

  dim3 gg(C_ / 128, RX / 128);
  mma_gemm_kernel<true><<<gg, 256, SMEM_MMA>>>(
      pxnh, pxnl, pwqh, pwql, bq, pq, pqf, 0.125f);
  mma_gemm_half_kernel<<<gg, 256, SMEM_HALF>>>(pynf, pwkf, bk, pkf);
  mma_gemm_half_kernel<<<gg, 256, SMEM_HALF>>>(pynf, pwvf, bv, pvf);
  vtrans_kernel<<<dim3(M_ / 64, B_ * H_), 256>>>();

  scores_mma_kernel<<<dim3(M_ / 128, N_ / 128, B_ * H_), 256, SMEM_HALF>>>();
  av_fused_kernel<<<dim3(N_ / 32, B_), 512, SMEM_AVF>>>();

  mma_gemm_kernel<false><<<gg, 256, SMEM_MMA>>>(
      pdh, pdl, pwch, pwcl, bc, ph, nullptr, 0.f);
  final_kernel<<<RX, 128>>>(log_, lob, out);
}